// round 4
// baseline (speedup 1.0000x reference)
#include <cuda_runtime.h>
#include <cuda_bf16.h>

#define KST   256
#define DIM   256
#define VOC   50000
#define TT    512
#define BBAT  256
#define KP1   257
#define MDIM  512
#define NROWS (KP1*KP1)
#define LN_EPS 1e-5f
#define NEGINF (__int_as_float(0xff800000))
#define NCB   391            // ceil(50000/128)

__device__ __nv_bfloat16 g_h_bf[KST*DIM];
__device__ float g_h32[KST*DIM];
__device__ float g_P[KP1*MDIM];
__device__ float g_Q[KP1*MDIM];
__device__ __nv_bfloat16 g_tdw_bf[KST*MDIM];
__device__ float g_logZ_em[KST];
__device__ float g_em_pmax[KST*NCB];
__device__ float g_em_psum[KST*NCB];
__device__ float g_translp[(size_t)NROWS*KST];

__device__ __forceinline__ void mma16816(float* c,
    unsigned a0, unsigned a1, unsigned a2, unsigned a3, unsigned b0, unsigned b1)
{
    asm volatile(
        "mma.sync.aligned.m16n8k16.row.col.f32.bf16.bf16.f32 "
        "{%0,%1,%2,%3}, {%4,%5,%6,%7}, {%8,%9}, {%0,%1,%2,%3};\n"
        : "+f"(c[0]), "+f"(c[1]), "+f"(c[2]), "+f"(c[3])
        : "r"(a0), "r"(a1), "r"(a2), "r"(a3), "r"(b0), "r"(b1));
}

// ---- A: emission MLP -> h (fp32 + bf16) ; one block per state k ----
__global__ __launch_bounds__(DIM) void nhmm_kA(
    const float* __restrict__ lembs, const float* __restrict__ emW,
    const float* __restrict__ em_bias, const float* __restrict__ em_g,
    const float* __restrict__ em_beta)
{
    __shared__ float le[DIM];
    __shared__ float ws[8], ws2[8];
    int k = blockIdx.x, c = threadIdx.x;
    le[c] = lembs[k*DIM + c];
    __syncthreads();
    const float4* w4 = reinterpret_cast<const float4*>(emW + (size_t)c*DIM);
    float acc = 0.f;
    #pragma unroll 8
    for (int d4 = 0; d4 < DIM/4; d4++) {
        float4 w = w4[d4];
        acc += le[4*d4]*w.x + le[4*d4+1]*w.y + le[4*d4+2]*w.z + le[4*d4+3]*w.w;
    }
    float p = le[c] + fmaxf(acc + em_bias[c], 0.f);
    float s = p, s2 = p*p;
    #pragma unroll
    for (int o = 16; o; o >>= 1) {
        s  += __shfl_xor_sync(0xffffffffu, s,  o);
        s2 += __shfl_xor_sync(0xffffffffu, s2, o);
    }
    if ((c & 31) == 0) { ws[c>>5] = s; ws2[c>>5] = s2; }
    __syncthreads();
    float S = 0.f, S2 = 0.f;
    #pragma unroll
    for (int w = 0; w < 8; w++) { S += ws[w]; S2 += ws2[w]; }
    float mu = S * (1.f/DIM);
    float rstd = rsqrtf(S2*(1.f/DIM) - mu*mu + LN_EPS);
    float h = (p - mu)*rstd*em_g[c] + em_beta[c];
    g_h32[k*DIM + c] = h;
    g_h_bf[k*DIM + c] = __float2bfloat16(h);
}

// ---- B: P,Q = tlembs @ tm_W halves (+bias folded into P) ; block per col c ----
__global__ __launch_bounds__(256) void nhmm_kB(
    const float* __restrict__ tlembs, const float* __restrict__ tmW,
    const float* __restrict__ tm_bias)
{
    __shared__ float w1[DIM], w2[DIM];
    int c = blockIdx.x, t = threadIdx.x;
    w1[t] = tmW[(size_t)c*MDIM + t];
    w2[t] = tmW[(size_t)c*MDIM + DIM + t];
    __syncthreads();
    float bias = tm_bias[c];
    for (int i = t; i < KP1; i += 256) {
        const float4* tl4 = reinterpret_cast<const float4*>(tlembs + (size_t)i*DIM);
        float a1 = 0.f, a2 = 0.f;
        #pragma unroll 8
        for (int d4 = 0; d4 < DIM/4; d4++) {
            float4 v = tl4[d4];
            a1 += v.x*w1[4*d4] + v.y*w1[4*d4+1] + v.z*w1[4*d4+2] + v.w*w1[4*d4+3];
            a2 += v.x*w2[4*d4] + v.y*w2[4*d4+1] + v.z*w2[4*d4+2] + v.w*w2[4*d4+3];
        }
        g_P[i*MDIM + c] = a1 + bias;
        g_Q[i*MDIM + c] = a2;
    }
}

// ---- conv: td_W -> bf16 ----
__global__ void nhmm_kConv(const float* __restrict__ tdW)
{
    int idx = blockIdx.x*blockDim.x + threadIdx.x;
    if (idx < KST*MDIM) g_tdw_bf[idx] = __float2bfloat16(tdW[idx]);
}

// ---- C: emission partial logsumexp over V (no logit store) ----
// smem: A_s 64x264 bf16 @0 (33792) | W_s 128x72 bf16 @33792 (18432)
//       L_s 64x132 f32 @52224 (33792) | decb_s 128 f32 @86016 -> 86528 total
#define C_SMEM 86528
__global__ __launch_bounds__(256) void nhmm_kC(
    const float* __restrict__ decW, const float* __restrict__ decb)
{
    extern __shared__ char sm[];
    __nv_bfloat16* A_s = reinterpret_cast<__nv_bfloat16*>(sm);
    __nv_bfloat16* W_s = reinterpret_cast<__nv_bfloat16*>(sm + 33792);
    float* L_s    = reinterpret_cast<float*>(sm + 52224);
    float* decb_s = reinterpret_cast<float*>(sm + 86016);
    const int ASTR = 264, WSTR = 72, LSTR = 132;

    int cb = blockIdx.x, rb = blockIdx.y;
    int n0 = cb * 128, r0 = rb * 64;
    int tid = threadIdx.x, warp = tid >> 5, lane = tid & 31;
    int wr = warp >> 1, wc = warp & 1;
    int gid = lane >> 2, tg = lane & 3;
    int arow0 = wr*16 + gid;

    {   // stage A tile (64 x 256 bf16)
        int row = tid >> 2, kb = (tid & 3) * 64;
        const uint4* src = reinterpret_cast<const uint4*>(&g_h_bf[(r0+row)*DIM + kb]);
        uint4* dst = reinterpret_cast<uint4*>(&A_s[row*ASTR + kb]);
        #pragma unroll
        for (int u = 0; u < 8; u++) dst[u] = src[u];
    }
    if (tid < 128) decb_s[tid] = (n0 + tid < VOC) ? decb[n0 + tid] : 0.f;

    float acc[8][4] = {};
    for (int kc = 0; kc < DIM; kc += 64) {
        __syncthreads();
        {   // stage W chunk: 128 n x 64 k, fp32 -> bf16
            int n = tid >> 1, kb = (tid & 1) * 32;
            bool valid = (n0 + n) < VOC;
            const float* src = decW + (size_t)(n0+n)*DIM + kc + kb;
            __nv_bfloat16* dst = &W_s[n*WSTR + kb];
            #pragma unroll
            for (int u = 0; u < 32; u += 4) {
                float4 w = valid ? *reinterpret_cast<const float4*>(src + u)
                                 : make_float4(0.f,0.f,0.f,0.f);
                dst[u]   = __float2bfloat16(w.x); dst[u+1] = __float2bfloat16(w.y);
                dst[u+2] = __float2bfloat16(w.z); dst[u+3] = __float2bfloat16(w.w);
            }
        }
        __syncthreads();
        #pragma unroll
        for (int ks = 0; ks < 64; ks += 16) {
            int ka = kc + ks;
            unsigned A0 = *reinterpret_cast<const unsigned*>(&A_s[(arow0  )*ASTR + ka + 2*tg]);
            unsigned A1 = *reinterpret_cast<const unsigned*>(&A_s[(arow0+8)*ASTR + ka + 2*tg]);
            unsigned A2 = *reinterpret_cast<const unsigned*>(&A_s[(arow0  )*ASTR + ka + 2*tg + 8]);
            unsigned A3 = *reinterpret_cast<const unsigned*>(&A_s[(arow0+8)*ASTR + ka + 2*tg + 8]);
            #pragma unroll
            for (int f = 0; f < 8; f++) {
                int n = wc*64 + f*8 + gid;
                unsigned B0 = *reinterpret_cast<const unsigned*>(&W_s[n*WSTR + ks + 2*tg]);
                unsigned B1 = *reinterpret_cast<const unsigned*>(&W_s[n*WSTR + ks + 2*tg + 8]);
                mma16816(acc[f], A0, A1, A2, A3, B0, B1);
            }
        }
    }
    __syncthreads();
    #pragma unroll
    for (int f = 0; f < 8; f++) {
        int cl = wc*64 + f*8 + 2*tg;
        float b0 = decb_s[cl], b1 = decb_s[cl+1];
        L_s[(arow0  )*LSTR + cl  ] = acc[f][0] + b0;
        L_s[(arow0  )*LSTR + cl+1] = acc[f][1] + b1;
        L_s[(arow0+8)*LSTR + cl  ] = acc[f][2] + b0;
        L_s[(arow0+8)*LSTR + cl+1] = acc[f][3] + b1;
    }
    __syncthreads();
    #pragma unroll
    for (int rr = 0; rr < 8; rr++) {
        int row = warp*8 + rr;
        float v[4]; float m = NEGINF;
        #pragma unroll
        for (int u = 0; u < 4; u++) {
            int col = lane + 32*u;
            v[u] = (n0 + col < VOC) ? L_s[row*LSTR + col] : NEGINF;
            m = fmaxf(m, v[u]);
        }
        #pragma unroll
        for (int o = 16; o; o >>= 1) m = fmaxf(m, __shfl_xor_sync(0xffffffffu, m, o));
        float s = 0.f;
        #pragma unroll
        for (int u = 0; u < 4; u++) s += (v[u] == NEGINF) ? 0.f : __expf(v[u] - m);
        #pragma unroll
        for (int o = 16; o; o >>= 1) s += __shfl_xor_sync(0xffffffffu, s, o);
        if (lane == 0) {
            g_em_pmax[(r0+row)*NCB + cb] = m;
            g_em_psum[(r0+row)*NCB + cb] = s;
        }
    }
}

// ---- Cred: combine partial lse -> logZ_em ----
__global__ __launch_bounds__(KST) void nhmm_kCred()
{
    int k = threadIdx.x;
    float m = NEGINF;
    for (int cb = 0; cb < NCB; cb++) m = fmaxf(m, g_em_pmax[k*NCB + cb]);
    float s = 0.f;
    for (int cb = 0; cb < NCB; cb++)
        s += __expf(g_em_pmax[k*NCB + cb] - m) * g_em_psum[k*NCB + cb];
    g_logZ_em[k] = m + logf(s);
}

// ---- D: transition rows (8i x 8j tile) -> normalized log-probs ----
// smem offsets (bytes):
//  Pt 0(16384) Qt 16384 TLi 32768(8192) TLj 40960 g 49152(2048) beta 51200
//  tdb 53248(1024) red 54272(1024) lse 55296(256) th 55552(66560) Wt 122112(36864)
#define D_SMEM 158976
__global__ __launch_bounds__(256) void nhmm_kD(
    const float* __restrict__ tlembs, const float* __restrict__ tn_g,
    const float* __restrict__ tn_beta, const float* __restrict__ tdb)
{
    extern __shared__ char sm[];
    float* Pt    = reinterpret_cast<float*>(sm);
    float* Qt    = reinterpret_cast<float*>(sm + 16384);
    float* TLi   = reinterpret_cast<float*>(sm + 32768);
    float* TLj   = reinterpret_cast<float*>(sm + 40960);
    float* g_s   = reinterpret_cast<float*>(sm + 49152);
    float* be_s  = reinterpret_cast<float*>(sm + 51200);
    float* tdb_s = reinterpret_cast<float*>(sm + 53248);
    float2* red  = reinterpret_cast<float2*>(sm + 54272);
    float* lse_s = reinterpret_cast<float*>(sm + 55296);
    __nv_bfloat16* th_s = reinterpret_cast<__nv_bfloat16*>(sm + 55552);
    __nv_bfloat16* Wt   = reinterpret_cast<__nv_bfloat16*>(sm + 122112);
    const int THSTR = 520, WSTR = 72;

    int ib = blockIdx.x, jb = blockIdx.y;
    int tid = threadIdx.x, warp = tid >> 5, lane = tid & 31;
    int wr = warp >> 1, wc = warp & 1;
    int gid = lane >> 2, tg = lane & 3;

    for (int idx = tid; idx < 8*MDIM; idx += 256) {
        int r = idx >> 9, c = idx & 511;
        Pt[idx] = g_P[min(ib*8+r,256)*MDIM + c];
        Qt[idx] = g_Q[min(jb*8+r,256)*MDIM + c];
    }
    for (int idx = tid; idx < 8*DIM; idx += 256) {
        int r = idx >> 8, c = idx & 255;
        TLi[idx] = tlembs[min(ib*8+r,256)*DIM + c];
        TLj[idx] = tlembs[min(jb*8+r,256)*DIM + c];
    }
    for (int idx = tid; idx < MDIM; idx += 256) { g_s[idx] = tn_g[idx]; be_s[idx] = tn_beta[idx]; }
    if (tid < KST) tdb_s[tid] = tdb[tid];
    __syncthreads();

    // th = LN(cat + relu(P[i]+Q[j])) per row; warp handles 8 rows
    for (int q = 0; q < 8; q++) {
        int r = warp*8 + q, ir = r >> 3, jr = r & 7;
        float v[16]; float s = 0.f, s2 = 0.f;
        #pragma unroll
        for (int u = 0; u < 16; u++) {
            int c = u*32 + lane;
            float pre = Pt[ir*MDIM + c] + Qt[jr*MDIM + c];
            float cat = (c < DIM) ? TLi[ir*DIM + c] : TLj[jr*DIM + (c - DIM)];
            float vv = cat + fmaxf(pre, 0.f);
            v[u] = vv; s += vv; s2 += vv*vv;
        }
        #pragma unroll
        for (int o = 16; o; o >>= 1) {
            s  += __shfl_xor_sync(0xffffffffu, s,  o);
            s2 += __shfl_xor_sync(0xffffffffu, s2, o);
        }
        float mu = s * (1.f/MDIM);
        float rstd = rsqrtf(s2*(1.f/MDIM) - mu*mu + LN_EPS);
        #pragma unroll
        for (int u = 0; u < 16; u++) {
            int c = u*32 + lane;
            th_s[r*THSTR + c] = __float2bfloat16((v[u]-mu)*rstd*g_s[c] + be_s[c]);
        }
    }

    float acc[16][4] = {};
    for (int kc = 0; kc < MDIM; kc += 64) {
        __syncthreads();
        {   // stage td_W chunk: 256 n x 64 k bf16
            const uint4* src = reinterpret_cast<const uint4*>(&g_tdw_bf[tid*MDIM + kc]);
            uint4* dst = reinterpret_cast<uint4*>(&Wt[tid*WSTR]);
            #pragma unroll
            for (int u = 0; u < 8; u++) dst[u] = src[u];
        }
        __syncthreads();
        #pragma unroll
        for (int ks = 0; ks < 64; ks += 16) {
            int k = kc + ks;
            unsigned A0 = *reinterpret_cast<const unsigned*>(&th_s[(wr*16+gid  )*THSTR + k + 2*tg]);
            unsigned A1 = *reinterpret_cast<const unsigned*>(&th_s[(wr*16+gid+8)*THSTR + k + 2*tg]);
            unsigned A2 = *reinterpret_cast<const unsigned*>(&th_s[(wr*16+gid  )*THSTR + k + 2*tg + 8]);
            unsigned A3 = *reinterpret_cast<const unsigned*>(&th_s[(wr*16+gid+8)*THSTR + k + 2*tg + 8]);
            #pragma unroll
            for (int f = 0; f < 16; f++) {
                int n = wc*128 + f*8 + gid;
                unsigned B0 = *reinterpret_cast<const unsigned*>(&Wt[n*WSTR + ks + 2*tg]);
                unsigned B1 = *reinterpret_cast<const unsigned*>(&Wt[n*WSTR + ks + 2*tg + 8]);
                mma16816(acc[f], A0, A1, A2, A3, B0, B1);
            }
        }
    }

    // fold bias, per-row logsumexp (row split across wc halves + quad lanes)
    int rA = wr*16 + gid, rB = rA + 8;
    float m0 = NEGINF, m1 = NEGINF;
    #pragma unroll
    for (int f = 0; f < 16; f++) {
        int n = wc*128 + f*8 + 2*tg;
        acc[f][0] += tdb_s[n]; acc[f][1] += tdb_s[n+1];
        acc[f][2] += tdb_s[n]; acc[f][3] += tdb_s[n+1];
        m0 = fmaxf(m0, fmaxf(acc[f][0], acc[f][1]));
        m1 = fmaxf(m1, fmaxf(acc[f][2], acc[f][3]));
    }
    m0 = fmaxf(m0, __shfl_xor_sync(0xffffffffu, m0, 1));
    m0 = fmaxf(m0, __shfl_xor_sync(0xffffffffu, m0, 2));
    m1 = fmaxf(m1, __shfl_xor_sync(0xffffffffu, m1, 1));
    m1 = fmaxf(m1, __shfl_xor_sync(0xffffffffu, m1, 2));
    float s0 = 0.f, s1 = 0.f;
    #pragma unroll
    for (int f = 0; f < 16; f++) {
        s0 += __expf(acc[f][0]-m0) + __expf(acc[f][1]-m0);
        s1 += __expf(acc[f][2]-m1) + __expf(acc[f][3]-m1);
    }
    s0 += __shfl_xor_sync(0xffffffffu, s0, 1);
    s0 += __shfl_xor_sync(0xffffffffu, s0, 2);
    s1 += __shfl_xor_sync(0xffffffffu, s1, 1);
    s1 += __shfl_xor_sync(0xffffffffu, s1, 2);
    if (tg == 0) { red[rA*2 + wc] = make_float2(m0, s0); red[rB*2 + wc] = make_float2(m1, s1); }
    __syncthreads();
    if (tid < 64) {
        float2 a = red[tid*2], b = red[tid*2+1];
        float M = fmaxf(a.x, b.x);
        lse_s[tid] = M + logf(__expf(a.x-M)*a.y + __expf(b.x-M)*b.y);
    }
    __syncthreads();

    int iA = ib*8 + (rA>>3), jA = jb*8 + (rA&7);
    int iB = ib*8 + (rB>>3), jB = jb*8 + (rB&7);
    if (iA < KP1 && jA < KP1) {
        size_t base = (size_t)(iA*KP1 + jA)*KST;
        float l = lse_s[rA];
        #pragma unroll
        for (int f = 0; f < 16; f++) {
            int n = wc*128 + f*8 + 2*tg;
            g_translp[base+n]   = acc[f][0] - l;
            g_translp[base+n+1] = acc[f][1] - l;
        }
    }
    if (iB < KP1 && jB < KP1) {
        size_t base = (size_t)(iB*KP1 + jB)*KST;
        float l = lse_s[rB];
        #pragma unroll
        for (int f = 0; f < 16; f++) {
            int n = wc*128 + f*8 + 2*tg;
            g_translp[base+n]   = acc[f][2] - l;
            g_translp[base+n+1] = acc[f][3] - l;
        }
    }
}

// ---- E: final gather + per-batch reduction ; one block per b ----
__global__ __launch_bounds__(256) void nhmm_kE(
    const int* __restrict__ x, const int* __restrict__ z,
    const float* __restrict__ decW, const float* __restrict__ decb,
    float* __restrict__ out)
{
    __shared__ float part[8];
    int b = blockIdx.x, tid = threadIdx.x, warp = tid >> 5, lane = tid & 31;
    float accw = 0.f;
    for (int t = warp; t < TT; t += 8) {
        int xv = x[t*BBAT + b], zv = z[t*BBAT + b];
        int w0 = (t >= 2) ? z[(t-2)*BBAT + b] : KST;
        int w1 = (t >= 1) ? z[(t-1)*BBAT + b] : KST;
        const float4* ha = reinterpret_cast<const float4*>(&g_h32[zv*DIM]);
        const float4* wa = reinterpret_cast<const float4*>(&decW[(size_t)xv*DIM]);
        float d = 0.f;
        #pragma unroll
        for (int u = 0; u < 2; u++) {
            float4 hv = ha[lane*2+u], wv = wa[lane*2+u];
            d += hv.x*wv.x + hv.y*wv.y + hv.z*wv.z + hv.w*wv.w;
        }
        #pragma unroll
        for (int o = 16; o; o >>= 1) d += __shfl_xor_sync(0xffffffffu, d, o);
        if (lane == 0)
            accw += d + decb[xv] - g_logZ_em[zv]
                  + g_translp[(size_t)(w0*KP1 + w1)*KST + zv];
    }
    if (lane == 0) part[warp] = accw;
    __syncthreads();
    if (tid == 0) {
        float s = 0.f;
        for (int w = 0; w < 8; w++) s += part[w];
        out[b] = s;
    }
}

extern "C" void kernel_launch(void* const* d_in, const int* in_sizes, int n_in,
                              void* d_out, int out_size)
{
    const int*   x       = (const int*)d_in[0];
    const int*   z       = (const int*)d_in[1];
    const float* lembs   = (const float*)d_in[2];
    const float* tlembs  = (const float*)d_in[3];
    const float* decW    = (const float*)d_in[4];
    const float* decb    = (const float*)d_in[5];
    const float* emW     = (const float*)d_in[6];
    const float* em_bias = (const float*)d_in[7];
    const float* em_g    = (const float*)d_in[8];
    const float* em_beta = (const float*)d_in[9];
    const float* tdW     = (const float*)d_in[10];
    const float* tdb     = (const float*)d_in[11];
    const float* tmW     = (const float*)d_in[12];
    const float* tm_bias = (const float*)d_in[13];
    const float* tn_g    = (const float*)d_in[14];
    const float* tn_beta = (const float*)d_in[15];
    float* out = (float*)d_out;

    cudaFuncSetAttribute(nhmm_kC, cudaFuncAttributeMaxDynamicSharedMemorySize, C_SMEM);
    cudaFuncSetAttribute(nhmm_kD, cudaFuncAttributeMaxDynamicSharedMemorySize, D_SMEM);

    nhmm_kA<<<KST, DIM>>>(lembs, emW, em_bias, em_g, em_beta);
    nhmm_kB<<<MDIM, 256>>>(tlembs, tmW, tm_bias);
    nhmm_kConv<<<(KST*MDIM + 255)/256, 256>>>(tdW);
    nhmm_kC<<<dim3(NCB, 4), 256, C_SMEM>>>(decW, decb);
    nhmm_kCred<<<1, KST>>>();
    nhmm_kD<<<dim3(33, 33), 256, D_SMEM>>>(tlembs, tn_g, tn_beta, tdb);
    nhmm_kE<<<BBAT, 256>>>(x, z, decW, decb, out);
}

// round 5
// speedup vs baseline: 1.1188x; 1.1188x over previous
#include <cuda_runtime.h>
#include <cuda_bf16.h>

#define KST   256
#define DIM   256
#define VOC   50000
#define TT    512
#define BBAT  256
#define KP1   257
#define MDIM  512
#define NROWS (KP1*KP1)
#define LN_EPS 1e-5f
#define NEGINF (__int_as_float(0xff800000))
#define NCB   391            // ceil(50000/128)

__device__ __nv_bfloat16 g_h_bf[KST*DIM];
__device__ float g_h32[KST*DIM];
__device__ float g_P[KP1*MDIM];
__device__ float g_Q[KP1*MDIM];
__device__ __nv_bfloat16 g_tdw_bf[KST*MDIM];
__device__ float g_logZ_em[KST];
__device__ float g_em_pmax[KST*NCB];
__device__ float g_em_psum[KST*NCB];
__device__ float g_translp[(size_t)NROWS*KST];
__device__ float g_epart[BBAT*8];

__device__ __forceinline__ void mma16816(float* c,
    unsigned a0, unsigned a1, unsigned a2, unsigned a3, unsigned b0, unsigned b1)
{
    asm volatile(
        "mma.sync.aligned.m16n8k16.row.col.f32.bf16.bf16.f32 "
        "{%0,%1,%2,%3}, {%4,%5,%6,%7}, {%8,%9}, {%0,%1,%2,%3};\n"
        : "+f"(c[0]), "+f"(c[1]), "+f"(c[2]), "+f"(c[3])
        : "r"(a0), "r"(a1), "r"(a2), "r"(a3), "r"(b0), "r"(b1));
}
__device__ __forceinline__ void ldsm4(unsigned& r0, unsigned& r1, unsigned& r2, unsigned& r3,
                                      unsigned addr)
{
    asm volatile("ldmatrix.sync.aligned.m8n8.x4.shared.b16 {%0,%1,%2,%3}, [%4];"
        : "=r"(r0), "=r"(r1), "=r"(r2), "=r"(r3) : "r"(addr));
}
__device__ __forceinline__ unsigned smem_u32(const void* p)
{
    return (unsigned)__cvta_generic_to_shared(p);
}
__device__ __forceinline__ unsigned bf2u(__nv_bfloat162 v)
{
    return *reinterpret_cast<unsigned*>(&v);
}

// ---- A: emission MLP -> h (fp32 + bf16) ; one block per state k ----
__global__ __launch_bounds__(DIM) void nhmm_kA(
    const float* __restrict__ lembs, const float* __restrict__ emW,
    const float* __restrict__ em_bias, const float* __restrict__ em_g,
    const float* __restrict__ em_beta)
{
    __shared__ float le[DIM];
    __shared__ float ws[8], ws2[8];
    int k = blockIdx.x, c = threadIdx.x;
    le[c] = lembs[k*DIM + c];
    __syncthreads();
    const float4* w4 = reinterpret_cast<const float4*>(emW + (size_t)c*DIM);
    float acc = 0.f;
    #pragma unroll 8
    for (int d4 = 0; d4 < DIM/4; d4++) {
        float4 w = w4[d4];
        acc += le[4*d4]*w.x + le[4*d4+1]*w.y + le[4*d4+2]*w.z + le[4*d4+3]*w.w;
    }
    float p = le[c] + fmaxf(acc + em_bias[c], 0.f);
    float s = p, s2 = p*p;
    #pragma unroll
    for (int o = 16; o; o >>= 1) {
        s  += __shfl_xor_sync(0xffffffffu, s,  o);
        s2 += __shfl_xor_sync(0xffffffffu, s2, o);
    }
    if ((c & 31) == 0) { ws[c>>5] = s; ws2[c>>5] = s2; }
    __syncthreads();
    float S = 0.f, S2 = 0.f;
    #pragma unroll
    for (int w = 0; w < 8; w++) { S += ws[w]; S2 += ws2[w]; }
    float mu = S * (1.f/DIM);
    float rstd = rsqrtf(S2*(1.f/DIM) - mu*mu + LN_EPS);
    float h = (p - mu)*rstd*em_g[c] + em_beta[c];
    g_h32[k*DIM + c] = h;
    g_h_bf[k*DIM + c] = __float2bfloat16(h);
}

// ---- B: P,Q = tlembs @ tm_W halves (+bias into P) ; block per col c ----
__global__ __launch_bounds__(256) void nhmm_kB(
    const float* __restrict__ tlembs, const float* __restrict__ tmW,
    const float* __restrict__ tm_bias)
{
    __shared__ float w1[DIM], w2[DIM];
    int c = blockIdx.x, t = threadIdx.x;
    w1[t] = tmW[(size_t)c*MDIM + t];
    w2[t] = tmW[(size_t)c*MDIM + DIM + t];
    __syncthreads();
    float bias = tm_bias[c];
    for (int i = t; i < KP1; i += 256) {
        const float4* tl4 = reinterpret_cast<const float4*>(tlembs + (size_t)i*DIM);
        float a1 = 0.f, a2 = 0.f;
        #pragma unroll 8
        for (int d4 = 0; d4 < DIM/4; d4++) {
            float4 v = tl4[d4];
            a1 += v.x*w1[4*d4] + v.y*w1[4*d4+1] + v.z*w1[4*d4+2] + v.w*w1[4*d4+3];
            a2 += v.x*w2[4*d4] + v.y*w2[4*d4+1] + v.z*w2[4*d4+2] + v.w*w2[4*d4+3];
        }
        g_P[i*MDIM + c] = a1 + bias;
        g_Q[i*MDIM + c] = a2;
    }
}

// ---- conv: td_W -> bf16 ----
__global__ void nhmm_kConv(const float* __restrict__ tdW)
{
    int idx = blockIdx.x*blockDim.x + threadIdx.x;
    if (idx < KST*MDIM) g_tdw_bf[idx] = __float2bfloat16(tdW[idx]);
}

// ---- C: emission partial logsumexp over V ----
// one block per 128-col vocab tile; loops over all 4 row-blocks (dec_W read once)
// smem: W_s 128x264 bf16 @0 (67584) | A_s 64x264 bf16 @67584 (33792)
//       decb 128 f32 @101376 (512) | red 64x2 float2 @101888 (1024) -> 102912
#define C_WSTR 264
#define C_ASTR 264
#define C_SMEM 102912
__global__ __launch_bounds__(256) void nhmm_kC(
    const float* __restrict__ decW, const float* __restrict__ decb)
{
    extern __shared__ char sm[];
    __nv_bfloat16* W_s = reinterpret_cast<__nv_bfloat16*>(sm);
    __nv_bfloat16* A_s = reinterpret_cast<__nv_bfloat16*>(sm + 67584);
    float* decb_s = reinterpret_cast<float*>(sm + 101376);
    float2* red   = reinterpret_cast<float2*>(sm + 101888);

    int cb = blockIdx.x;
    int n0 = cb * 128;
    int tid = threadIdx.x, warp = tid >> 5, lane = tid & 31;
    int wr = warp >> 1, wc = warp & 1;
    int gid = lane >> 2, tg = lane & 3;

    // stage W tile 128n x 256k, fp32 -> bf16, packed 16B stores
    {
        int n = tid >> 1, k0 = (tid & 1) * 128;
        bool valid = (n0 + n) < VOC;
        const float4* src = reinterpret_cast<const float4*>(decW + (size_t)(n0+n)*DIM + k0);
        uint4* dst = reinterpret_cast<uint4*>(&W_s[n*C_WSTR + k0]);
        #pragma unroll
        for (int u = 0; u < 16; u++) {
            float4 a = valid ? src[2*u]   : make_float4(0.f,0.f,0.f,0.f);
            float4 b = valid ? src[2*u+1] : make_float4(0.f,0.f,0.f,0.f);
            uint4 v;
            v.x = bf2u(__floats2bfloat162_rn(a.x, a.y));
            v.y = bf2u(__floats2bfloat162_rn(a.z, a.w));
            v.z = bf2u(__floats2bfloat162_rn(b.x, b.y));
            v.w = bf2u(__floats2bfloat162_rn(b.z, b.w));
            dst[u] = v;
        }
    }
    if (tid < 128) decb_s[tid] = (n0 + tid < VOC) ? decb[n0 + tid] : 0.f;

    // per-lane ldmatrix bases
    unsigned A_u = smem_u32(A_s), W_u = smem_u32(W_s);
    int a_row = wr*16 + (lane & 15);
    int a_k8  = (lane >> 4) * 8;
    unsigned a_base = A_u + (unsigned)(a_row*C_ASTR + a_k8)*2u;
    int b_r = lane & 7, b_seg = lane >> 3;
    int b_row0 = ((b_seg >> 1) & 1)*8 + b_r;
    int b_k8 = (b_seg & 1)*8;
    unsigned b_base = W_u + (unsigned)(b_row0*C_WSTR + b_k8)*2u;

    for (int rb = 0; rb < 4; rb++) {
        int r0 = rb * 64;
        __syncthreads();
        {   // stage A 64x256 bf16
            int row = tid >> 2, kb = (tid & 3) * 64;
            const uint4* src = reinterpret_cast<const uint4*>(&g_h_bf[(r0+row)*DIM + kb]);
            uint4* dst = reinterpret_cast<uint4*>(&A_s[row*C_ASTR + kb]);
            #pragma unroll
            for (int u = 0; u < 8; u++) dst[u] = src[u];
        }
        __syncthreads();

        float acc[8][4] = {};
        #pragma unroll
        for (int k = 0; k < DIM; k += 16) {
            unsigned a0, a1, a2, a3;
            ldsm4(a0, a1, a2, a3, a_base + (unsigned)k*2u);
            #pragma unroll
            for (int e = 0; e < 4; e++) {
                unsigned b0, b1, b2, b3;
                ldsm4(b0, b1, b2, b3,
                      b_base + (unsigned)((wc*64 + e*16)*C_WSTR + k)*2u);
                mma16816(acc[2*e],   a0, a1, a2, a3, b0, b1);
                mma16816(acc[2*e+1], a0, a1, a2, a3, b2, b3);
            }
        }

        // per-row logsumexp (mask invalid cols)
        int rA = wr*16 + gid, rB = rA + 8;
        float m0 = NEGINF, m1 = NEGINF;
        float v[8][4];
        #pragma unroll
        for (int f = 0; f < 8; f++) {
            int n = wc*64 + f*8 + 2*tg;
            bool ok0 = (n0 + n) < VOC, ok1 = (n0 + n + 1) < VOC;
            v[f][0] = ok0 ? acc[f][0] + decb_s[n]   : NEGINF;
            v[f][1] = ok1 ? acc[f][1] + decb_s[n+1] : NEGINF;
            v[f][2] = ok0 ? acc[f][2] + decb_s[n]   : NEGINF;
            v[f][3] = ok1 ? acc[f][3] + decb_s[n+1] : NEGINF;
            m0 = fmaxf(m0, fmaxf(v[f][0], v[f][1]));
            m1 = fmaxf(m1, fmaxf(v[f][2], v[f][3]));
        }
        m0 = fmaxf(m0, __shfl_xor_sync(0xffffffffu, m0, 1));
        m0 = fmaxf(m0, __shfl_xor_sync(0xffffffffu, m0, 2));
        m1 = fmaxf(m1, __shfl_xor_sync(0xffffffffu, m1, 1));
        m1 = fmaxf(m1, __shfl_xor_sync(0xffffffffu, m1, 2));
        float s0 = 0.f, s1 = 0.f;
        #pragma unroll
        for (int f = 0; f < 8; f++) {
            s0 += __expf(v[f][0]-m0) + __expf(v[f][1]-m0);
            s1 += __expf(v[f][2]-m1) + __expf(v[f][3]-m1);
        }
        s0 += __shfl_xor_sync(0xffffffffu, s0, 1);
        s0 += __shfl_xor_sync(0xffffffffu, s0, 2);
        s1 += __shfl_xor_sync(0xffffffffu, s1, 1);
        s1 += __shfl_xor_sync(0xffffffffu, s1, 2);
        if (tg == 0) {
            red[rA*2 + wc] = make_float2(m0, s0);
            red[rB*2 + wc] = make_float2(m1, s1);
        }
        __syncthreads();
        if (tid < 64) {
            float2 a = red[tid*2], b = red[tid*2+1];
            float M = fmaxf(a.x, b.x);
            g_em_pmax[(r0+tid)*NCB + cb] = M;
            g_em_psum[(r0+tid)*NCB + cb] = __expf(a.x-M)*a.y + __expf(b.x-M)*b.y;
        }
    }
}

// ---- Cred: combine partial lse -> logZ_em ----
__global__ __launch_bounds__(KST) void nhmm_kCred()
{
    int k = threadIdx.x;
    float m = NEGINF;
    for (int cb = 0; cb < NCB; cb++) m = fmaxf(m, g_em_pmax[k*NCB + cb]);
    float s = 0.f;
    for (int cb = 0; cb < NCB; cb++)
        s += __expf(g_em_pmax[k*NCB + cb] - m) * g_em_psum[k*NCB + cb];
    g_logZ_em[k] = m + logf(s);
}

// ---- D: transition rows (8i x 8j tile) -> normalized log-probs ----
// smem: Pt 0(16384) Qt 16384 TLi 32768(8192) TLj 40960 g 49152(2048) beta 51200
//       tdb 53248(1024) red 54272(1024) lse 55296(256)
//       th/Ot 55552(66560) Wt 122112(36864) -> 158976
#define D_THSTR 520
#define D_OSTR  260
#define D_WSTR  72
#define D_SMEM 158976
__global__ __launch_bounds__(256) void nhmm_kD(
    const float* __restrict__ tlembs, const float* __restrict__ tn_g,
    const float* __restrict__ tn_beta, const float* __restrict__ tdb)
{
    extern __shared__ char sm[];
    float* Pt    = reinterpret_cast<float*>(sm);
    float* Qt    = reinterpret_cast<float*>(sm + 16384);
    float* TLi   = reinterpret_cast<float*>(sm + 32768);
    float* TLj   = reinterpret_cast<float*>(sm + 40960);
    float* g_s   = reinterpret_cast<float*>(sm + 49152);
    float* be_s  = reinterpret_cast<float*>(sm + 51200);
    float* tdb_s = reinterpret_cast<float*>(sm + 53248);
    float2* red  = reinterpret_cast<float2*>(sm + 54272);
    float* lse_s = reinterpret_cast<float*>(sm + 55296);
    __nv_bfloat16* th_s = reinterpret_cast<__nv_bfloat16*>(sm + 55552);
    float* Ot = reinterpret_cast<float*>(sm + 55552);        // reuses th after mma
    __nv_bfloat16* Wt = reinterpret_cast<__nv_bfloat16*>(sm + 122112);

    int ib = blockIdx.x, jb = blockIdx.y;
    int tid = threadIdx.x, warp = tid >> 5, lane = tid & 31;
    int wr = warp >> 1, wc = warp & 1;
    int gid = lane >> 2, tg = lane & 3;

    for (int idx = tid; idx < 8*MDIM; idx += 256) {
        int r = idx >> 9, c = idx & 511;
        Pt[idx] = g_P[min(ib*8+r,256)*MDIM + c];
        Qt[idx] = g_Q[min(jb*8+r,256)*MDIM + c];
    }
    for (int idx = tid; idx < 8*DIM; idx += 256) {
        int r = idx >> 8, c = idx & 255;
        TLi[idx] = tlembs[min(ib*8+r,256)*DIM + c];
        TLj[idx] = tlembs[min(jb*8+r,256)*DIM + c];
    }
    for (int idx = tid; idx < MDIM; idx += 256) { g_s[idx] = tn_g[idx]; be_s[idx] = tn_beta[idx]; }
    if (tid < KST) tdb_s[tid] = tdb[tid];
    __syncthreads();

    // th = LN(cat + relu(P[i]+Q[j])) ; lane owns 16 contiguous cols -> packed stores
    for (int q = 0; q < 8; q++) {
        int r = warp*8 + q, ir = r >> 3, jr = r & 7;
        int c0 = lane * 16;
        const float4* pp = reinterpret_cast<const float4*>(&Pt[ir*MDIM + c0]);
        const float4* qq = reinterpret_cast<const float4*>(&Qt[jr*MDIM + c0]);
        const float4* cc = (c0 < DIM)
            ? reinterpret_cast<const float4*>(&TLi[ir*DIM + c0])
            : reinterpret_cast<const float4*>(&TLj[jr*DIM + (c0 - DIM)]);
        float vv[16]; float s = 0.f, s2 = 0.f;
        #pragma unroll
        for (int u = 0; u < 4; u++) {
            float4 p = pp[u], qv = qq[u], cv = cc[u];
            float w0 = cv.x + fmaxf(p.x+qv.x, 0.f);
            float w1 = cv.y + fmaxf(p.y+qv.y, 0.f);
            float w2 = cv.z + fmaxf(p.z+qv.z, 0.f);
            float w3 = cv.w + fmaxf(p.w+qv.w, 0.f);
            vv[4*u]=w0; vv[4*u+1]=w1; vv[4*u+2]=w2; vv[4*u+3]=w3;
            s += w0+w1+w2+w3;
            s2 += w0*w0+w1*w1+w2*w2+w3*w3;
        }
        #pragma unroll
        for (int o = 16; o; o >>= 1) {
            s  += __shfl_xor_sync(0xffffffffu, s,  o);
            s2 += __shfl_xor_sync(0xffffffffu, s2, o);
        }
        float mu = s * (1.f/MDIM);
        float rstd = rsqrtf(s2*(1.f/MDIM) - mu*mu + LN_EPS);
        #pragma unroll
        for (int u = 0; u < 2; u++) {
            int cbx = c0 + 8*u;
            const float4* gg = reinterpret_cast<const float4*>(&g_s[cbx]);
            const float4* bb = reinterpret_cast<const float4*>(&be_s[cbx]);
            float4 g0 = gg[0], g1 = gg[1], b0 = bb[0], b1 = bb[1];
            float h0 = (vv[8*u  ]-mu)*rstd*g0.x + b0.x;
            float h1 = (vv[8*u+1]-mu)*rstd*g0.y + b0.y;
            float h2 = (vv[8*u+2]-mu)*rstd*g0.z + b0.z;
            float h3 = (vv[8*u+3]-mu)*rstd*g0.w + b0.w;
            float h4 = (vv[8*u+4]-mu)*rstd*g1.x + b1.x;
            float h5 = (vv[8*u+5]-mu)*rstd*g1.y + b1.y;
            float h6 = (vv[8*u+6]-mu)*rstd*g1.z + b1.z;
            float h7 = (vv[8*u+7]-mu)*rstd*g1.w + b1.w;
            uint4 o4;
            o4.x = bf2u(__floats2bfloat162_rn(h0, h1));
            o4.y = bf2u(__floats2bfloat162_rn(h2, h3));
            o4.z = bf2u(__floats2bfloat162_rn(h4, h5));
            o4.w = bf2u(__floats2bfloat162_rn(h6, h7));
            *reinterpret_cast<uint4*>(&th_s[r*D_THSTR + cbx]) = o4;
        }
    }

    // ldmatrix bases
    unsigned TH_u = smem_u32(th_s), W_u = smem_u32(Wt);
    int a_row = wr*16 + (lane & 15);
    int a_k8  = (lane >> 4) * 8;
    unsigned a_base = TH_u + (unsigned)(a_row*D_THSTR + a_k8)*2u;
    int b_r = lane & 7, b_seg = lane >> 3;
    int b_row0 = ((b_seg >> 1) & 1)*8 + b_r;
    int b_k8 = (b_seg & 1)*8;
    unsigned b_base = W_u + (unsigned)(b_row0*D_WSTR + b_k8)*2u;

    float acc[16][4] = {};
    for (int kc = 0; kc < MDIM; kc += 64) {
        __syncthreads();
        {   // stage td_W chunk 256n x 64k bf16
            const uint4* src = reinterpret_cast<const uint4*>(&g_tdw_bf[tid*MDIM + kc]);
            uint4* dst = reinterpret_cast<uint4*>(&Wt[tid*D_WSTR]);
            #pragma unroll
            for (int u = 0; u < 8; u++) dst[u] = src[u];
        }
        __syncthreads();
        #pragma unroll
        for (int ks = 0; ks < 64; ks += 16) {
            unsigned a0, a1, a2, a3;
            ldsm4(a0, a1, a2, a3, a_base + (unsigned)(kc + ks)*2u);
            #pragma unroll
            for (int e = 0; e < 8; e++) {
                unsigned b0, b1, b2, b3;
                ldsm4(b0, b1, b2, b3,
                      b_base + (unsigned)((wc*128 + e*16)*D_WSTR + ks)*2u);
                mma16816(acc[2*e],   a0, a1, a2, a3, b0, b1);
                mma16816(acc[2*e+1], a0, a1, a2, a3, b2, b3);
            }
        }
    }

    // bias fold + per-row logsumexp
    int rA = wr*16 + gid, rB = rA + 8;
    float m0 = NEGINF, m1 = NEGINF;
    #pragma unroll
    for (int f = 0; f < 16; f++) {
        int n = wc*128 + f*8 + 2*tg;
        acc[f][0] += tdb_s[n]; acc[f][1] += tdb_s[n+1];
        acc[f][2] += tdb_s[n]; acc[f][3] += tdb_s[n+1];
        m0 = fmaxf(m0, fmaxf(acc[f][0], acc[f][1]));
        m1 = fmaxf(m1, fmaxf(acc[f][2], acc[f][3]));
    }
    m0 = fmaxf(m0, __shfl_xor_sync(0xffffffffu, m0, 1));
    m0 = fmaxf(m0, __shfl_xor_sync(0xffffffffu, m0, 2));
    m1 = fmaxf(m1, __shfl_xor_sync(0xffffffffu, m1, 1));
    m1 = fmaxf(m1, __shfl_xor_sync(0xffffffffu, m1, 2));
    float s0 = 0.f, s1 = 0.f;
    #pragma unroll
    for (int f = 0; f < 16; f++) {
        s0 += __expf(acc[f][0]-m0) + __expf(acc[f][1]-m0);
        s1 += __expf(acc[f][2]-m1) + __expf(acc[f][3]-m1);
    }
    s0 += __shfl_xor_sync(0xffffffffu, s0, 1);
    s0 += __shfl_xor_sync(0xffffffffu, s0, 2);
    s1 += __shfl_xor_sync(0xffffffffu, s1, 1);
    s1 += __shfl_xor_sync(0xffffffffu, s1, 2);
    if (tg == 0) { red[rA*2 + wc] = make_float2(m0, s0); red[rB*2 + wc] = make_float2(m1, s1); }
    __syncthreads();
    if (tid < 64) {
        float2 a = red[tid*2], b = red[tid*2+1];
        float M = fmaxf(a.x, b.x);
        lse_s[tid] = M + logf(__expf(a.x-M)*a.y + __expf(b.x-M)*b.y);
    }
    __syncthreads();   // all warps past mma + lse ready -> th_s reusable as Ot

    {
        float lA = lse_s[rA], lB = lse_s[rB];
        #pragma unroll
        for (int f = 0; f < 16; f++) {
            int n = wc*128 + f*8 + 2*tg;
            *reinterpret_cast<float2*>(&Ot[rA*D_OSTR + n]) =
                make_float2(acc[f][0]-lA, acc[f][1]-lA);
            *reinterpret_cast<float2*>(&Ot[rB*D_OSTR + n]) =
                make_float2(acc[f][2]-lB, acc[f][3]-lB);
        }
    }
    __syncthreads();

    // coalesced copy Ot -> g_translp
    {
        int row = tid >> 2, kb = (tid & 3) * 64;
        int i = ib*8 + (row >> 3), j = jb*8 + (row & 7);
        if (i < KP1 && j < KP1) {
            const float4* src = reinterpret_cast<const float4*>(&Ot[row*D_OSTR + kb]);
            float4* dst = reinterpret_cast<float4*>(&g_translp[(size_t)(i*KP1 + j)*KST + kb]);
            #pragma unroll
            for (int u = 0; u < 16; u++) dst[u] = src[u];
        }
    }
}

// ---- E: gather + partial reduction ; block = (b, 64-t chunk) ----
__global__ __launch_bounds__(256) void nhmm_kE(
    const int* __restrict__ x, const int* __restrict__ z,
    const float* __restrict__ decW, const float* __restrict__ decb)
{
    __shared__ float part[8];
    int b = blockIdx.x, ty = blockIdx.y;
    int t0 = ty * 64;
    int tid = threadIdx.x, warp = tid >> 5, lane = tid & 31;
    float accw = 0.f;
    for (int q = 0; q < 8; q++) {
        int t = t0 + warp + 8*q;
        int xv = x[t*BBAT + b], zv = z[t*BBAT + b];
        int w0 = (t >= 2) ? z[(t-2)*BBAT + b] : KST;
        int w1 = (t >= 1) ? z[(t-1)*BBAT + b] : KST;
        const float4* ha = reinterpret_cast<const float4*>(&g_h32[zv*DIM]);
        const float4* wa = reinterpret_cast<const float4*>(&decW[(size_t)xv*DIM]);
        float d = 0.f;
        #pragma unroll
        for (int u = 0; u < 2; u++) {
            float4 hv = ha[lane*2+u], wv = wa[lane*2+u];
            d += hv.x*wv.x + hv.y*wv.y + hv.z*wv.z + hv.w*wv.w;
        }
        #pragma unroll
        for (int o = 16; o; o >>= 1) d += __shfl_xor_sync(0xffffffffu, d, o);
        if (lane == 0)
            accw += d + decb[xv] - g_logZ_em[zv]
                  + g_translp[(size_t)(w0*KP1 + w1)*KST + zv];
    }
    if (lane == 0) part[warp] = accw;
    __syncthreads();
    if (tid == 0) {
        float s = 0.f;
        for (int w = 0; w < 8; w++) s += part[w];
        g_epart[b*8 + ty] = s;
    }
}

__global__ __launch_bounds__(BBAT) void nhmm_kEred(float* __restrict__ out)
{
    int b = threadIdx.x;
    float s = 0.f;
    #pragma unroll
    for (int q = 0; q < 8; q++) s += g_epart[b*8 + q];
    out[b] = s;
}

extern "C" void kernel_launch(void* const* d_in, const int* in_sizes, int n_in,
                              void* d_out, int out_size)
{
    const int*   x       = (const int*)d_in[0];
    const int*   z       = (const int*)d_in[1];
    const float* lembs   = (const float*)d_in[2];
    const float* tlembs  = (const float*)d_in[3];
    const float* decW    = (const float*)d_in[4];
    const float* decb    = (const float*)d_in[5];
    const float* emW     = (const float*)d_in[6];
    const float* em_bias = (const float*)d_in[7];
    const float* em_g    = (const float*)d_in[8];
    const float* em_beta = (const float*)d_in[9];
    const float* tdW     = (const float*)d_in[10];
    const float* tdb     = (const float*)d_in[11];
    const float* tmW     = (const float*)d_in[12];
    const float* tm_bias = (const float*)d_in[13];
    const float* tn_g    = (const float*)d_in[14];
    const float* tn_beta = (const float*)d_in[15];
    float* out = (float*)d_out;

    cudaFuncSetAttribute(nhmm_kC, cudaFuncAttributeMaxDynamicSharedMemorySize, C_SMEM);
    cudaFuncSetAttribute(nhmm_kD, cudaFuncAttributeMaxDynamicSharedMemorySize, D_SMEM);

    nhmm_kA<<<KST, DIM>>>(lembs, emW, em_bias, em_g, em_beta);
    nhmm_kB<<<MDIM, 256>>>(tlembs, tmW, tm_bias);
    nhmm_kConv<<<(KST*MDIM + 255)/256, 256>>>(tdW);
    nhmm_kC<<<NCB, 256, C_SMEM>>>(decW, decb);
    nhmm_kCred<<<1, KST>>>();
    nhmm_kD<<<dim3(33, 33), 256, D_SMEM>>>(tlembs, tn_g, tn_beta, tdb);
    nhmm_kE<<<dim3(BBAT, 8), 256>>>(x, z, decW, decb);
    nhmm_kEred<<<1, BBAT>>>(out);
}

// round 8
// speedup vs baseline: 1.6598x; 1.4836x over previous
#include <cuda_runtime.h>
#include <cuda_bf16.h>

#define KST   256
#define DIM   256
#define VOC   50000
#define TT    512
#define BBAT  256
#define KP1   257
#define MDIM  512
#define NROWS (KP1*KP1)
#define LN_EPS 1e-5f
#define NEGINF (__int_as_float(0xff800000))
#define NCB   391            // ceil(50000/128)

__device__ __nv_bfloat16 g_h_bf[KST*DIM];
__device__ float g_h32[KST*DIM];
__device__ float g_P[KP1*MDIM];
__device__ float g_Q[KP1*MDIM];
__device__ __nv_bfloat16 g_tdw_bf[KST*MDIM];
__device__ float g_logZ_em[KST];
__device__ float g_em_pmax[KST*NCB];
__device__ float g_em_psum[KST*NCB];
__device__ float g_translp[(size_t)NROWS*KST];
__device__ float g_epart[BBAT*8];

__device__ __forceinline__ void mma16816(float* c,
    unsigned a0, unsigned a1, unsigned a2, unsigned a3, unsigned b0, unsigned b1)
{
    asm volatile(
        "mma.sync.aligned.m16n8k16.row.col.f32.bf16.bf16.f32 "
        "{%0,%1,%2,%3}, {%4,%5,%6,%7}, {%8,%9}, {%0,%1,%2,%3};\n"
        : "+f"(c[0]), "+f"(c[1]), "+f"(c[2]), "+f"(c[3])
        : "r"(a0), "r"(a1), "r"(a2), "r"(a3), "r"(b0), "r"(b1));
}
__device__ __forceinline__ void ldsm4(unsigned& r0, unsigned& r1, unsigned& r2, unsigned& r3,
                                      unsigned addr)
{
    asm volatile("ldmatrix.sync.aligned.m8n8.x4.shared.b16 {%0,%1,%2,%3}, [%4];"
        : "=r"(r0), "=r"(r1), "=r"(r2), "=r"(r3) : "r"(addr));
}
__device__ __forceinline__ unsigned smem_u32(const void* p)
{
    return (unsigned)__cvta_generic_to_shared(p);
}
__device__ __forceinline__ unsigned bf2u(__nv_bfloat162 v)
{
    return *reinterpret_cast<unsigned*>(&v);
}
__device__ __forceinline__ float2 u2f2(unsigned u)
{
    __nv_bfloat162 b = *reinterpret_cast<__nv_bfloat162*>(&u);
    return __bfloat1622float2(b);
}
__device__ __forceinline__ uint4 f8_to_bf8(float4 a, float4 b)
{
    uint4 v;
    v.x = bf2u(__floats2bfloat162_rn(a.x, a.y));
    v.y = bf2u(__floats2bfloat162_rn(a.z, a.w));
    v.z = bf2u(__floats2bfloat162_rn(b.x, b.y));
    v.w = bf2u(__floats2bfloat162_rn(b.z, b.w));
    return v;
}

// ---- A: emission MLP -> h (fp32 + bf16) ; one block per state k ----
__global__ __launch_bounds__(DIM) void nhmm_kA(
    const float* __restrict__ lembs, const float* __restrict__ emW,
    const float* __restrict__ em_bias, const float* __restrict__ em_g,
    const float* __restrict__ em_beta)
{
    __shared__ float le[DIM];
    __shared__ float ws[8], ws2[8];
    int k = blockIdx.x, c = threadIdx.x;
    le[c] = lembs[k*DIM + c];
    __syncthreads();
    const float4* w4 = reinterpret_cast<const float4*>(emW + (size_t)c*DIM);
    float acc = 0.f;
    #pragma unroll 8
    for (int d4 = 0; d4 < DIM/4; d4++) {
        float4 w = w4[d4];
        acc += le[4*d4]*w.x + le[4*d4+1]*w.y + le[4*d4+2]*w.z + le[4*d4+3]*w.w;
    }
    float p = le[c] + fmaxf(acc + em_bias[c], 0.f);
    float s = p, s2 = p*p;
    #pragma unroll
    for (int o = 16; o; o >>= 1) {
        s  += __shfl_xor_sync(0xffffffffu, s,  o);
        s2 += __shfl_xor_sync(0xffffffffu, s2, o);
    }
    if ((c & 31) == 0) { ws[c>>5] = s; ws2[c>>5] = s2; }
    __syncthreads();
    float S = 0.f, S2 = 0.f;
    #pragma unroll
    for (int w = 0; w < 8; w++) { S += ws[w]; S2 += ws2[w]; }
    float mu = S * (1.f/DIM);
    float rstd = rsqrtf(S2*(1.f/DIM) - mu*mu + LN_EPS);
    float h = (p - mu)*rstd*em_g[c] + em_beta[c];
    g_h32[k*DIM + c] = h;
    g_h_bf[k*DIM + c] = __float2bfloat16(h);
}

// ---- B: P,Q = tlembs @ tm_W halves (+bias into P) ; block per col c ----
__global__ __launch_bounds__(256) void nhmm_kB(
    const float* __restrict__ tlembs, const float* __restrict__ tmW,
    const float* __restrict__ tm_bias)
{
    __shared__ float w1[DIM], w2[DIM];
    int c = blockIdx.x, t = threadIdx.x;
    w1[t] = tmW[(size_t)c*MDIM + t];
    w2[t] = tmW[(size_t)c*MDIM + DIM + t];
    __syncthreads();
    float bias = tm_bias[c];
    for (int i = t; i < KP1; i += 256) {
        const float4* tl4 = reinterpret_cast<const float4*>(tlembs + (size_t)i*DIM);
        float a1 = 0.f, a2 = 0.f;
        #pragma unroll 8
        for (int d4 = 0; d4 < DIM/4; d4++) {
            float4 v = tl4[d4];
            a1 += v.x*w1[4*d4] + v.y*w1[4*d4+1] + v.z*w1[4*d4+2] + v.w*w1[4*d4+3];
            a2 += v.x*w2[4*d4] + v.y*w2[4*d4+1] + v.z*w2[4*d4+2] + v.w*w2[4*d4+3];
        }
        g_P[i*MDIM + c] = a1 + bias;
        g_Q[i*MDIM + c] = a2;
    }
}

// ---- conv: td_W -> bf16 ----
__global__ void nhmm_kConv(const float* __restrict__ tdW)
{
    int idx = blockIdx.x*blockDim.x + threadIdx.x;
    if (idx < KST*MDIM) g_tdw_bf[idx] = __float2bfloat16(tdW[idx]);
}

// ---- C: emission partial logsumexp over V ----
#define C_WSTR 264
#define C_ASTR 264
#define C_SMEM 102912
__global__ __launch_bounds__(256) void nhmm_kC(
    const float* __restrict__ decW, const float* __restrict__ decb)
{
    extern __shared__ char sm[];
    __nv_bfloat16* W_s = reinterpret_cast<__nv_bfloat16*>(sm);
    __nv_bfloat16* A_s = reinterpret_cast<__nv_bfloat16*>(sm + 67584);
    float* decb_s = reinterpret_cast<float*>(sm + 101376);
    float2* red   = reinterpret_cast<float2*>(sm + 101888);

    int cb = blockIdx.x;
    int n0 = cb * 128;
    int tid = threadIdx.x, warp = tid >> 5, lane = tid & 31;
    int wr = warp >> 1, wc = warp & 1;
    int gid = lane >> 2, tg = lane & 3;

    {
        int n = tid >> 1, k0 = (tid & 1) * 128;
        bool valid = (n0 + n) < VOC;
        const float4* src = reinterpret_cast<const float4*>(decW + (size_t)(n0+n)*DIM + k0);
        uint4* dst = reinterpret_cast<uint4*>(&W_s[n*C_WSTR + k0]);
        #pragma unroll
        for (int u = 0; u < 16; u++) {
            float4 a = valid ? src[2*u]   : make_float4(0.f,0.f,0.f,0.f);
            float4 b = valid ? src[2*u+1] : make_float4(0.f,0.f,0.f,0.f);
            dst[u] = f8_to_bf8(a, b);
        }
    }
    if (tid < 128) decb_s[tid] = (n0 + tid < VOC) ? decb[n0 + tid] : 0.f;

    unsigned A_u = smem_u32(A_s), W_u = smem_u32(W_s);
    int a_row = wr*16 + (lane & 15);
    int a_k8  = (lane >> 4) * 8;
    unsigned a_base = A_u + (unsigned)(a_row*C_ASTR + a_k8)*2u;
    int b_r = lane & 7, b_seg = lane >> 3;
    int b_row0 = ((b_seg >> 1) & 1)*8 + b_r;
    int b_k8 = (b_seg & 1)*8;
    unsigned b_base = W_u + (unsigned)(b_row0*C_WSTR + b_k8)*2u;

    for (int rb = 0; rb < 4; rb++) {
        int r0 = rb * 64;
        __syncthreads();
        {
            int row = tid >> 2, kb = (tid & 3) * 64;
            const uint4* src = reinterpret_cast<const uint4*>(&g_h_bf[(r0+row)*DIM + kb]);
            uint4* dst = reinterpret_cast<uint4*>(&A_s[row*C_ASTR + kb]);
            #pragma unroll
            for (int u = 0; u < 8; u++) dst[u] = src[u];
        }
        __syncthreads();

        float acc[8][4] = {};
        #pragma unroll
        for (int k = 0; k < DIM; k += 16) {
            unsigned a0, a1, a2, a3;
            ldsm4(a0, a1, a2, a3, a_base + (unsigned)k*2u);
            #pragma unroll
            for (int e = 0; e < 4; e++) {
                unsigned b0, b1, b2, b3;
                ldsm4(b0, b1, b2, b3,
                      b_base + (unsigned)((wc*64 + e*16)*C_WSTR + k)*2u);
                mma16816(acc[2*e],   a0, a1, a2, a3, b0, b1);
                mma16816(acc[2*e+1], a0, a1, a2, a3, b2, b3);
            }
        }

        int rA = wr*16 + gid, rB = rA + 8;
        float m0 = NEGINF, m1 = NEGINF;
        float v[8][4];
        #pragma unroll
        for (int f = 0; f < 8; f++) {
            int n = wc*64 + f*8 + 2*tg;
            bool ok0 = (n0 + n) < VOC, ok1 = (n0 + n + 1) < VOC;
            v[f][0] = ok0 ? acc[f][0] + decb_s[n]   : NEGINF;
            v[f][1] = ok1 ? acc[f][1] + decb_s[n+1] : NEGINF;
            v[f][2] = ok0 ? acc[f][2] + decb_s[n]   : NEGINF;
            v[f][3] = ok1 ? acc[f][3] + decb_s[n+1] : NEGINF;
            m0 = fmaxf(m0, fmaxf(v[f][0], v[f][1]));
            m1 = fmaxf(m1, fmaxf(v[f][2], v[f][3]));
        }
        m0 = fmaxf(m0, __shfl_xor_sync(0xffffffffu, m0, 1));
        m0 = fmaxf(m0, __shfl_xor_sync(0xffffffffu, m0, 2));
        m1 = fmaxf(m1, __shfl_xor_sync(0xffffffffu, m1, 1));
        m1 = fmaxf(m1, __shfl_xor_sync(0xffffffffu, m1, 2));
        float s0 = 0.f, s1 = 0.f;
        #pragma unroll
        for (int f = 0; f < 8; f++) {
            s0 += __expf(v[f][0]-m0) + __expf(v[f][1]-m0);
            s1 += __expf(v[f][2]-m1) + __expf(v[f][3]-m1);
        }
        s0 += __shfl_xor_sync(0xffffffffu, s0, 1);
        s0 += __shfl_xor_sync(0xffffffffu, s0, 2);
        s1 += __shfl_xor_sync(0xffffffffu, s1, 1);
        s1 += __shfl_xor_sync(0xffffffffu, s1, 2);
        if (tg == 0) {
            red[rA*2 + wc] = make_float2(m0, s0);
            red[rB*2 + wc] = make_float2(m1, s1);
        }
        __syncthreads();
        if (tid < 64) {
            float2 a = red[tid*2], b = red[tid*2+1];
            float M = fmaxf(a.x, b.x);
            g_em_pmax[(r0+tid)*NCB + cb] = M;
            g_em_psum[(r0+tid)*NCB + cb] = __expf(a.x-M)*a.y + __expf(b.x-M)*b.y;
        }
    }
}

// ---- Cred: combine partial lse -> logZ_em ; one warp per state ----
__global__ __launch_bounds__(32) void nhmm_kCred()
{
    int k = blockIdx.x, lane = threadIdx.x;
    float m = NEGINF;
    for (int cb = lane; cb < NCB; cb += 32) m = fmaxf(m, g_em_pmax[k*NCB + cb]);
    #pragma unroll
    for (int o = 16; o; o >>= 1) m = fmaxf(m, __shfl_xor_sync(0xffffffffu, m, o));
    float s = 0.f;
    for (int cb = lane; cb < NCB; cb += 32)
        s += __expf(g_em_pmax[k*NCB + cb] - m) * g_em_psum[k*NCB + cb];
    #pragma unroll
    for (int o = 16; o; o >>= 1) s += __shfl_xor_sync(0xffffffffu, s, o);
    if (lane == 0) g_logZ_em[k] = m + logf(s);
}

// ---- D: transition rows, 128-row (16i x 8j) tiles, 512 threads ----
// smem bytes: th/Ot 0..133120 | Wt 133120(36864) | PtB 169984(16384)
//  QtB 186368(8192) | TLiB 194560(8192) | TLjB 202752(4096) | g 206848(2048)
//  beta 208896(2048) | tdb 210944(1024) | red 211968(2048) | lse 214016(512)
#define D_THSTR 520
#define D_OSTR  260
#define D_WSTR  72
#define D_SMEM 214528
__global__ __launch_bounds__(512) void nhmm_kD(
    const float* __restrict__ tlembs, const float* __restrict__ tn_g,
    const float* __restrict__ tn_beta, const float* __restrict__ tdb)
{
    extern __shared__ char sm[];
    __nv_bfloat16* th_s = reinterpret_cast<__nv_bfloat16*>(sm);
    float* Ot           = reinterpret_cast<float*>(sm);           // reuse after mma
    __nv_bfloat16* Wt   = reinterpret_cast<__nv_bfloat16*>(sm + 133120);
    __nv_bfloat16* PtB  = reinterpret_cast<__nv_bfloat16*>(sm + 169984);
    __nv_bfloat16* QtB  = reinterpret_cast<__nv_bfloat16*>(sm + 186368);
    __nv_bfloat16* TLiB = reinterpret_cast<__nv_bfloat16*>(sm + 194560);
    __nv_bfloat16* TLjB = reinterpret_cast<__nv_bfloat16*>(sm + 202752);
    float* g_s   = reinterpret_cast<float*>(sm + 206848);
    float* be_s  = reinterpret_cast<float*>(sm + 208896);
    float* tdb_s = reinterpret_cast<float*>(sm + 210944);
    float2* red  = reinterpret_cast<float2*>(sm + 211968);
    float* lse_s = reinterpret_cast<float*>(sm + 214016);

    int ib = blockIdx.x, jb = blockIdx.y;
    int tid = threadIdx.x, warp = tid >> 5, lane = tid & 31;
    int wr = warp >> 1, wc = warp & 1;
    int gid = lane >> 2, tg = lane & 3;

    // stage P (16x512), Q (8x512), TLi (16x256), TLj (8x256) as bf16
    #pragma unroll
    for (int it = 0; it < 2; it++) {
        int e = (tid + it*512) * 8;                 // 16*512 = 8192 elems
        int r = e >> 9, c = e & 511;
        const float4* s4 = reinterpret_cast<const float4*>(&g_P[min(ib*16+r,256)*MDIM + c]);
        *reinterpret_cast<uint4*>(&PtB[r*512 + c]) = f8_to_bf8(s4[0], s4[1]);
    }
    {
        int e = tid * 8;                            // 8*512 = 4096 elems
        int r = e >> 9, c = e & 511;
        const float4* s4 = reinterpret_cast<const float4*>(&g_Q[min(jb*8+r,256)*MDIM + c]);
        *reinterpret_cast<uint4*>(&QtB[r*512 + c]) = f8_to_bf8(s4[0], s4[1]);
    }
    {
        int e = tid * 8;                            // 16*256 = 4096 elems
        int r = e >> 8, c = e & 255;
        const float4* s4 = reinterpret_cast<const float4*>(&tlembs[min(ib*16+r,256)*DIM + c]);
        *reinterpret_cast<uint4*>(&TLiB[r*256 + c]) = f8_to_bf8(s4[0], s4[1]);
    }
    if (tid < 256) {
        int e = tid * 8;                            // 8*256 = 2048 elems
        int r = e >> 8, c = e & 255;
        const float4* s4 = reinterpret_cast<const float4*>(&tlembs[min(jb*8+r,256)*DIM + c]);
        *reinterpret_cast<uint4*>(&TLjB[r*256 + c]) = f8_to_bf8(s4[0], s4[1]);
    }
    g_s[tid] = tn_g[tid];
    be_s[tid] = tn_beta[tid];
    if (tid < KST) tdb_s[tid] = tdb[tid];
    __syncthreads();

    // th = LN(cat + relu(P[i]+Q[j])) ; warp handles 8 rows, lane owns 16 cols
    for (int q = 0; q < 8; q++) {
        int r = warp*8 + q, ir = r >> 3, jr = r & 7;
        int c0 = lane * 16;
        const uint4* pp = reinterpret_cast<const uint4*>(&PtB[ir*512 + c0]);
        const uint4* qq = reinterpret_cast<const uint4*>(&QtB[jr*512 + c0]);
        const uint4* cc = (c0 < DIM)
            ? reinterpret_cast<const uint4*>(&TLiB[ir*DIM + c0])
            : reinterpret_cast<const uint4*>(&TLjB[jr*DIM + (c0 - DIM)]);
        uint4 pv[2] = {pp[0], pp[1]};
        uint4 qv[2] = {qq[0], qq[1]};
        uint4 cv[2] = {cc[0], cc[1]};
        const unsigned* pw = reinterpret_cast<const unsigned*>(pv);
        const unsigned* qw = reinterpret_cast<const unsigned*>(qv);
        const unsigned* cw = reinterpret_cast<const unsigned*>(cv);
        float vv[16]; float s = 0.f, s2 = 0.f;
        #pragma unroll
        for (int u = 0; u < 8; u++) {
            float2 pf = u2f2(pw[u]), qf = u2f2(qw[u]), cf = u2f2(cw[u]);
            float w0 = cf.x + fmaxf(pf.x + qf.x, 0.f);
            float w1 = cf.y + fmaxf(pf.y + qf.y, 0.f);
            vv[2*u] = w0; vv[2*u+1] = w1;
            s += w0 + w1; s2 += w0*w0 + w1*w1;
        }
        #pragma unroll
        for (int o = 16; o; o >>= 1) {
            s  += __shfl_xor_sync(0xffffffffu, s,  o);
            s2 += __shfl_xor_sync(0xffffffffu, s2, o);
        }
        float mu = s * (1.f/MDIM);
        float rstd = rsqrtf(s2*(1.f/MDIM) - mu*mu + LN_EPS);
        #pragma unroll
        for (int u = 0; u < 2; u++) {
            int cbx = c0 + 8*u;
            const float4* gg = reinterpret_cast<const float4*>(&g_s[cbx]);
            const float4* bb = reinterpret_cast<const float4*>(&be_s[cbx]);
            float4 g0 = gg[0], g1 = gg[1], b0 = bb[0], b1 = bb[1];
            float4 ha, hb;
            ha.x = (vv[8*u  ]-mu)*rstd*g0.x + b0.x;
            ha.y = (vv[8*u+1]-mu)*rstd*g0.y + b0.y;
            ha.z = (vv[8*u+2]-mu)*rstd*g0.z + b0.z;
            ha.w = (vv[8*u+3]-mu)*rstd*g0.w + b0.w;
            hb.x = (vv[8*u+4]-mu)*rstd*g1.x + b1.x;
            hb.y = (vv[8*u+5]-mu)*rstd*g1.y + b1.y;
            hb.z = (vv[8*u+6]-mu)*rstd*g1.z + b1.z;
            hb.w = (vv[8*u+7]-mu)*rstd*g1.w + b1.w;
            *reinterpret_cast<uint4*>(&th_s[r*D_THSTR + cbx]) = f8_to_bf8(ha, hb);
        }
    }

    unsigned TH_u = smem_u32(th_s), W_u = smem_u32(Wt);
    int a_row = wr*16 + (lane & 15);
    int a_k8  = (lane >> 4) * 8;
    unsigned a_base = TH_u + (unsigned)(a_row*D_THSTR + a_k8)*2u;
    int b_r = lane & 7, b_seg = lane >> 3;
    int b_row0 = ((b_seg >> 1) & 1)*8 + b_r;
    int b_k8 = (b_seg & 1)*8;
    unsigned b_base = W_u + (unsigned)(b_row0*D_WSTR + b_k8)*2u;

    float acc[16][4] = {};
    for (int kc = 0; kc < MDIM; kc += 64) {
        __syncthreads();
        {   // stage td_W chunk 256n x 64k bf16
            int n = tid >> 1, kb = (tid & 1) * 32;
            const uint4* src = reinterpret_cast<const uint4*>(&g_tdw_bf[n*MDIM + kc + kb]);
            uint4* dst = reinterpret_cast<uint4*>(&Wt[n*D_WSTR + kb]);
            #pragma unroll
            for (int u = 0; u < 4; u++) dst[u] = src[u];
        }
        __syncthreads();
        #pragma unroll
        for (int ks = 0; ks < 64; ks += 16) {
            unsigned a0, a1, a2, a3;
            ldsm4(a0, a1, a2, a3, a_base + (unsigned)(kc + ks)*2u);
            #pragma unroll
            for (int e = 0; e < 8; e++) {
                unsigned b0, b1, b2, b3;
                ldsm4(b0, b1, b2, b3,
                      b_base + (unsigned)((wc*128 + e*16)*D_WSTR + ks)*2u);
                mma16816(acc[2*e],   a0, a1, a2, a3, b0, b1);
                mma16816(acc[2*e+1], a0, a1, a2, a3, b2, b3);
            }
        }
    }

    // bias fold + per-row logsumexp
    int rA = wr*16 + gid, rB = rA + 8;
    float m0 = NEGINF, m1 = NEGINF;
    #pragma unroll
    for (int f = 0; f < 16; f++) {
        int n = wc*128 + f*8 + 2*tg;
        acc[f][0] += tdb_s[n]; acc[f][1] += tdb_s[n+1];
        acc[f][2] += tdb_s[n]; acc[f][3] += tdb_s[n+1];
        m0 = fmaxf(m0, fmaxf(acc[f][0], acc[f][1]));
        m1 = fmaxf(m1, fmaxf(acc[f][2], acc[f][3]));
    }
    m0 = fmaxf(m0, __shfl_xor_sync(0xffffffffu, m0, 1));
    m0 = fmaxf(m0, __shfl_xor_sync(0xffffffffu, m0, 2));
    m1 = fmaxf(m1, __shfl_xor_sync(0xffffffffu, m1, 1));
    m1 = fmaxf(m1, __shfl_xor_sync(0xffffffffu, m1, 2));
    float s0 = 0.f, s1 = 0.f;
    #pragma unroll
    for (int f = 0; f < 16; f++) {
        s0 += __expf(acc[f][0]-m0) + __expf(acc[f][1]-m0);
        s1 += __expf(acc[f][2]-m1) + __expf(acc[f][3]-m1);
    }
    s0 += __shfl_xor_sync(0xffffffffu, s0, 1);
    s0 += __shfl_xor_sync(0xffffffffu, s0, 2);
    s1 += __shfl_xor_sync(0xffffffffu, s1, 1);
    s1 += __shfl_xor_sync(0xffffffffu, s1, 2);
    if (tg == 0) { red[rA*2 + wc] = make_float2(m0, s0); red[rB*2 + wc] = make_float2(m1, s1); }
    __syncthreads();
    if (tid < 128) {
        float2 a = red[tid*2], b = red[tid*2+1];
        float M = fmaxf(a.x, b.x);
        lse_s[tid] = M + logf(__expf(a.x-M)*a.y + __expf(b.x-M)*b.y);
    }
    __syncthreads();   // everyone past mma reads -> th_s reusable as Ot

    {
        float lA = lse_s[rA], lB = lse_s[rB];
        #pragma unroll
        for (int f = 0; f < 16; f++) {
            int n = wc*128 + f*8 + 2*tg;
            *reinterpret_cast<float2*>(&Ot[rA*D_OSTR + n]) =
                make_float2(acc[f][0]-lA, acc[f][1]-lA);
            *reinterpret_cast<float2*>(&Ot[rB*D_OSTR + n]) =
                make_float2(acc[f][2]-lB, acc[f][3]-lB);
        }
    }
    __syncthreads();

    {   // coalesced copy Ot -> g_translp
        int row = tid >> 2, kb = (tid & 3) * 64;
        int i = ib*16 + (row >> 3), j = jb*8 + (row & 7);
        if (i < KP1 && j < KP1) {
            const float4* src = reinterpret_cast<const float4*>(&Ot[row*D_OSTR + kb]);
            float4* dst = reinterpret_cast<float4*>(&g_translp[(size_t)(i*KP1 + j)*KST + kb]);
            #pragma unroll
            for (int u = 0; u < 16; u++) dst[u] = src[u];
        }
    }
}

// ---- E: gather + partial reduction ----
__global__ __launch_bounds__(256) void nhmm_kE(
    const int* __restrict__ x, const int* __restrict__ z,
    const float* __restrict__ decW, const float* __restrict__ decb)
{
    __shared__ float part[8];
    int b = blockIdx.x, ty = blockIdx.y;
    int t0 = ty * 64;
    int tid = threadIdx.x, warp = tid >> 5, lane = tid & 31;
    float accw = 0.f;
    for (int q = 0; q < 8; q++) {
        int t = t0 + warp + 8*q;
        int xv = x[t*BBAT + b], zv = z[t*BBAT + b];
        int w0 = (t >= 2) ? z[(t-2)*BBAT + b] : KST;
        int w1 = (t >= 1) ? z[(t-1)*BBAT + b] : KST;
        const float4* ha = reinterpret_cast<const float4*>(&g_h32[zv*DIM]);
        const float4* wa = reinterpret_cast<const float4*>(&decW[(size_t)xv*DIM]);
        float d = 0.f;
        #pragma unroll
        for (int u = 0; u < 2; u++) {
            float4 hv = ha[lane*2+u], wv = wa[lane*2+u];
            d += hv.x*wv.x + hv.y*wv.y + hv.z*wv.z + hv.w*wv.w;
        }
        #pragma unroll
        for (int o = 16; o; o >>= 1) d += __shfl_xor_sync(0xffffffffu, d, o);
        if (lane == 0)
            accw += d + decb[xv] - g_logZ_em[zv]
                  + g_translp[(size_t)(w0*KP1 + w1)*KST + zv];
    }
    if (lane == 0) part[warp] = accw;
    __syncthreads();
    if (tid == 0) {
        float s = 0.f;
        for (int w = 0; w < 8; w++) s += part[w];
        g_epart[b*8 + ty] = s;
    }
}

__global__ __launch_bounds__(BBAT) void nhmm_kEred(float* __restrict__ out)
{
    int b = threadIdx.x;
    float s = 0.f;
    #pragma unroll
    for (int q = 0; q < 8; q++) s += g_epart[b*8 + q];
    out[b] = s;
}

extern "C" void kernel_launch(void* const* d_in, const int* in_sizes, int n_in,
                              void* d_out, int out_size)
{
    const int*   x       = (const int*)d_in[0];
    const int*   z       = (const int*)d_in[1];
    const float* lembs   = (const float*)d_in[2];
    const float* tlembs  = (const float*)d_in[3];
    const float* decW    = (const float*)d_in[4];
    const float* decb    = (const float*)d_in[5];
    const float* emW     = (const float*)d_in[6];
    const float* em_bias = (const float*)d_in[7];
    const float* em_g    = (const float*)d_in[8];
    const float* em_beta = (const float*)d_in[9];
    const float* tdW     = (const float*)d_in[10];
    const float* tdb     = (const float*)d_in[11];
    const float* tmW     = (const float*)d_in[12];
    const float* tm_bias = (const float*)d_in[13];
    const float* tn_g    = (const float*)d_in[14];
    const float* tn_beta = (const float*)d_in[15];
    float* out = (float*)d_out;

    cudaFuncSetAttribute(nhmm_kC, cudaFuncAttributeMaxDynamicSharedMemorySize, C_SMEM);
    cudaFuncSetAttribute(nhmm_kD, cudaFuncAttributeMaxDynamicSharedMemorySize, D_SMEM);

    nhmm_kA<<<KST, DIM>>>(lembs, emW, em_bias, em_g, em_beta);
    nhmm_kB<<<MDIM, 256>>>(tlembs, tmW, tm_bias);
    nhmm_kConv<<<(KST*MDIM + 255)/256, 256>>>(tdW);
    nhmm_kC<<<NCB, 256, C_SMEM>>>(decW, decb);
    nhmm_kCred<<<KST, 32>>>();
    nhmm_kD<<<dim3(17, 33), 512, D_SMEM>>>(tlembs, tn_g, tn_beta, tdb);
    nhmm_kE<<<dim3(BBAT, 8), 256>>>(x, z, decW, decb);
    nhmm_kEred<<<1, BBAT>>>(out);
}

// round 11
// speedup vs baseline: 1.9271x; 1.1610x over previous
#include <cuda_runtime.h>
#include <cuda_bf16.h>

#define KST   256
#define DIM   256
#define VOC   50000
#define TT    512
#define BBAT  256
#define KP1   257
#define MDIM  512
#define NROWS (KP1*KP1)
#define LN_EPS 1e-5f
#define NEGINF (__int_as_float(0xff800000))
#define NCB   391            // ceil(50000/128)

__device__ __nv_bfloat16 g_h_bf[KST*DIM];
__device__ float g_h32[KST*DIM];
__device__ float g_P[KP1*MDIM];
__device__ float g_Q[KP1*MDIM];
__device__ __nv_bfloat16 g_tdw_bf[KST*MDIM];
__device__ float g_logZ_em[KST];
__device__ float g_em_pmax[KST*NCB];
__device__ float g_em_psum[KST*NCB];
__device__ float g_translp[(size_t)NROWS*KST];
__device__ float g_epart[BBAT*8];

__device__ __forceinline__ void mma16816(float* c,
    unsigned a0, unsigned a1, unsigned a2, unsigned a3, unsigned b0, unsigned b1)
{
    asm volatile(
        "mma.sync.aligned.m16n8k16.row.col.f32.bf16.bf16.f32 "
        "{%0,%1,%2,%3}, {%4,%5,%6,%7}, {%8,%9}, {%0,%1,%2,%3};\n"
        : "+f"(c[0]), "+f"(c[1]), "+f"(c[2]), "+f"(c[3])
        : "r"(a0), "r"(a1), "r"(a2), "r"(a3), "r"(b0), "r"(b1));
}
__device__ __forceinline__ void ldsm4(unsigned& r0, unsigned& r1, unsigned& r2, unsigned& r3,
                                      unsigned addr)
{
    asm volatile("ldmatrix.sync.aligned.m8n8.x4.shared.b16 {%0,%1,%2,%3}, [%4];"
        : "=r"(r0), "=r"(r1), "=r"(r2), "=r"(r3) : "r"(addr));
}
__device__ __forceinline__ unsigned smem_u32(const void* p)
{
    return (unsigned)__cvta_generic_to_shared(p);
}
__device__ __forceinline__ void cp16(void* dst_smem, const void* src)
{
    unsigned d = smem_u32(dst_smem);
    asm volatile("cp.async.cg.shared.global [%0], [%1], 16;\n" :: "r"(d), "l"(src));
}
__device__ __forceinline__ unsigned bf2u(__nv_bfloat162 v)
{
    return *reinterpret_cast<unsigned*>(&v);
}
__device__ __forceinline__ float2 u2f2(unsigned u)
{
    __nv_bfloat162 b = *reinterpret_cast<__nv_bfloat162*>(&u);
    return __bfloat1622float2(b);
}
__device__ __forceinline__ uint4 f8_to_bf8(float4 a, float4 b)
{
    uint4 v;
    v.x = bf2u(__floats2bfloat162_rn(a.x, a.y));
    v.y = bf2u(__floats2bfloat162_rn(a.z, a.w));
    v.z = bf2u(__floats2bfloat162_rn(b.x, b.y));
    v.w = bf2u(__floats2bfloat162_rn(b.z, b.w));
    return v;
}

// ---- A: emission MLP -> h (fp32 + bf16) ; one block per state k ----
__global__ __launch_bounds__(DIM) void nhmm_kA(
    const float* __restrict__ lembs, const float* __restrict__ emW,
    const float* __restrict__ em_bias, const float* __restrict__ em_g,
    const float* __restrict__ em_beta)
{
    __shared__ float le[DIM];
    __shared__ float ws[8], ws2[8];
    int k = blockIdx.x, c = threadIdx.x;
    le[c] = lembs[k*DIM + c];
    __syncthreads();
    const float4* w4 = reinterpret_cast<const float4*>(emW + (size_t)c*DIM);
    float acc = 0.f;
    #pragma unroll 8
    for (int d4 = 0; d4 < DIM/4; d4++) {
        float4 w = w4[d4];
        acc += le[4*d4]*w.x + le[4*d4+1]*w.y + le[4*d4+2]*w.z + le[4*d4+3]*w.w;
    }
    float p = le[c] + fmaxf(acc + em_bias[c], 0.f);
    float s = p, s2 = p*p;
    #pragma unroll
    for (int o = 16; o; o >>= 1) {
        s  += __shfl_xor_sync(0xffffffffu, s,  o);
        s2 += __shfl_xor_sync(0xffffffffu, s2, o);
    }
    if ((c & 31) == 0) { ws[c>>5] = s; ws2[c>>5] = s2; }
    __syncthreads();
    float S = 0.f, S2 = 0.f;
    #pragma unroll
    for (int w = 0; w < 8; w++) { S += ws[w]; S2 += ws2[w]; }
    float mu = S * (1.f/DIM);
    float rstd = rsqrtf(S2*(1.f/DIM) - mu*mu + LN_EPS);
    float h = (p - mu)*rstd*em_g[c] + em_beta[c];
    g_h32[k*DIM + c] = h;
    g_h_bf[k*DIM + c] = __float2bfloat16(h);
}

// ---- B: P,Q = tlembs @ tm_W halves (+bias into P) ; block per col c ----
__global__ __launch_bounds__(256) void nhmm_kB(
    const float* __restrict__ tlembs, const float* __restrict__ tmW,
    const float* __restrict__ tm_bias)
{
    __shared__ float w1[DIM], w2[DIM];
    int c = blockIdx.x, t = threadIdx.x;
    w1[t] = tmW[(size_t)c*MDIM + t];
    w2[t] = tmW[(size_t)c*MDIM + DIM + t];
    __syncthreads();
    float bias = tm_bias[c];
    for (int i = t; i < KP1; i += 256) {
        const float4* tl4 = reinterpret_cast<const float4*>(tlembs + (size_t)i*DIM);
        float a1 = 0.f, a2 = 0.f;
        #pragma unroll 8
        for (int d4 = 0; d4 < DIM/4; d4++) {
            float4 v = tl4[d4];
            a1 += v.x*w1[4*d4] + v.y*w1[4*d4+1] + v.z*w1[4*d4+2] + v.w*w1[4*d4+3];
            a2 += v.x*w2[4*d4] + v.y*w2[4*d4+1] + v.z*w2[4*d4+2] + v.w*w2[4*d4+3];
        }
        g_P[i*MDIM + c] = a1 + bias;
        g_Q[i*MDIM + c] = a2;
    }
}

// ---- conv: td_W -> bf16 ----
__global__ void nhmm_kConv(const float* __restrict__ tdW)
{
    int idx = blockIdx.x*blockDim.x + threadIdx.x;
    if (idx < KST*MDIM) g_tdw_bf[idx] = __float2bfloat16(tdW[idx]);
}

// ---- C: emission partial logsumexp over V ----
#define C_WSTR 264
#define C_ASTR 264
#define C_SMEM 102912
__global__ __launch_bounds__(256) void nhmm_kC(
    const float* __restrict__ decW, const float* __restrict__ decb)
{
    extern __shared__ char sm[];
    __nv_bfloat16* W_s = reinterpret_cast<__nv_bfloat16*>(sm);
    __nv_bfloat16* A_s = reinterpret_cast<__nv_bfloat16*>(sm + 67584);
    float* decb_s = reinterpret_cast<float*>(sm + 101376);
    float2* red   = reinterpret_cast<float2*>(sm + 101888);

    int cb = blockIdx.x;
    int n0 = cb * 128;
    int tid = threadIdx.x, warp = tid >> 5, lane = tid & 31;
    int wr = warp >> 1, wc = warp & 1;
    int gid = lane >> 2, tg = lane & 3;

    {
        int n = tid >> 1, k0 = (tid & 1) * 128;
        bool valid = (n0 + n) < VOC;
        const float4* src = reinterpret_cast<const float4*>(decW + (size_t)(n0+n)*DIM + k0);
        uint4* dst = reinterpret_cast<uint4*>(&W_s[n*C_WSTR + k0]);
        #pragma unroll
        for (int u = 0; u < 16; u++) {
            float4 a = valid ? src[2*u]   : make_float4(0.f,0.f,0.f,0.f);
            float4 b = valid ? src[2*u+1] : make_float4(0.f,0.f,0.f,0.f);
            dst[u] = f8_to_bf8(a, b);
        }
    }
    if (tid < 128) decb_s[tid] = (n0 + tid < VOC) ? decb[n0 + tid] : 0.f;

    unsigned A_u = smem_u32(A_s), W_u = smem_u32(W_s);
    int a_row = wr*16 + (lane & 15);
    int a_k8  = (lane >> 4) * 8;
    unsigned a_base = A_u + (unsigned)(a_row*C_ASTR + a_k8)*2u;
    int b_r = lane & 7, b_seg = lane >> 3;
    int b_row0 = ((b_seg >> 1) & 1)*8 + b_r;
    int b_k8 = (b_seg & 1)*8;
    unsigned b_base = W_u + (unsigned)(b_row0*C_WSTR + b_k8)*2u;

    for (int rb = 0; rb < 4; rb++) {
        int r0 = rb * 64;
        __syncthreads();
        {
            int row = tid >> 2, kb = (tid & 3) * 64;
            const uint4* src = reinterpret_cast<const uint4*>(&g_h_bf[(r0+row)*DIM + kb]);
            uint4* dst = reinterpret_cast<uint4*>(&A_s[row*C_ASTR + kb]);
            #pragma unroll
            for (int u = 0; u < 8; u++) dst[u] = src[u];
        }
        __syncthreads();

        float acc[8][4] = {};
        #pragma unroll
        for (int k = 0; k < DIM; k += 16) {
            unsigned a0, a1, a2, a3;
            ldsm4(a0, a1, a2, a3, a_base + (unsigned)k*2u);
            #pragma unroll
            for (int e = 0; e < 4; e++) {
                unsigned b0, b1, b2, b3;
                ldsm4(b0, b1, b2, b3,
                      b_base + (unsigned)((wc*64 + e*16)*C_WSTR + k)*2u);
                mma16816(acc[2*e],   a0, a1, a2, a3, b0, b1);
                mma16816(acc[2*e+1], a0, a1, a2, a3, b2, b3);
            }
        }

        int rA = wr*16 + gid, rB = rA + 8;
        float m0 = NEGINF, m1 = NEGINF;
        float v[8][4];
        #pragma unroll
        for (int f = 0; f < 8; f++) {
            int n = wc*64 + f*8 + 2*tg;
            bool ok0 = (n0 + n) < VOC, ok1 = (n0 + n + 1) < VOC;
            v[f][0] = ok0 ? acc[f][0] + decb_s[n]   : NEGINF;
            v[f][1] = ok1 ? acc[f][1] + decb_s[n+1] : NEGINF;
            v[f][2] = ok0 ? acc[f][2] + decb_s[n]   : NEGINF;
            v[f][3] = ok1 ? acc[f][3] + decb_s[n+1] : NEGINF;
            m0 = fmaxf(m0, fmaxf(v[f][0], v[f][1]));
            m1 = fmaxf(m1, fmaxf(v[f][2], v[f][3]));
        }
        m0 = fmaxf(m0, __shfl_xor_sync(0xffffffffu, m0, 1));
        m0 = fmaxf(m0, __shfl_xor_sync(0xffffffffu, m0, 2));
        m1 = fmaxf(m1, __shfl_xor_sync(0xffffffffu, m1, 1));
        m1 = fmaxf(m1, __shfl_xor_sync(0xffffffffu, m1, 2));
        float s0 = 0.f, s1 = 0.f;
        #pragma unroll
        for (int f = 0; f < 8; f++) {
            s0 += __expf(v[f][0]-m0) + __expf(v[f][1]-m0);
            s1 += __expf(v[f][2]-m1) + __expf(v[f][3]-m1);
        }
        s0 += __shfl_xor_sync(0xffffffffu, s0, 1);
        s0 += __shfl_xor_sync(0xffffffffu, s0, 2);
        s1 += __shfl_xor_sync(0xffffffffu, s1, 1);
        s1 += __shfl_xor_sync(0xffffffffu, s1, 2);
        if (tg == 0) {
            red[rA*2 + wc] = make_float2(m0, s0);
            red[rB*2 + wc] = make_float2(m1, s1);
        }
        __syncthreads();
        if (tid < 64) {
            float2 a = red[tid*2], b = red[tid*2+1];
            float M = fmaxf(a.x, b.x);
            g_em_pmax[(r0+tid)*NCB + cb] = M;
            g_em_psum[(r0+tid)*NCB + cb] = __expf(a.x-M)*a.y + __expf(b.x-M)*b.y;
        }
    }
}

// ---- Cred: combine partial lse -> logZ_em ; one warp per state ----
__global__ __launch_bounds__(32) void nhmm_kCred()
{
    int k = blockIdx.x, lane = threadIdx.x;
    float m = NEGINF;
    for (int cb = lane; cb < NCB; cb += 32) m = fmaxf(m, g_em_pmax[k*NCB + cb]);
    #pragma unroll
    for (int o = 16; o; o >>= 1) m = fmaxf(m, __shfl_xor_sync(0xffffffffu, m, o));
    float s = 0.f;
    for (int cb = lane; cb < NCB; cb += 32)
        s += __expf(g_em_pmax[k*NCB + cb] - m) * g_em_psum[k*NCB + cb];
    #pragma unroll
    for (int o = 16; o; o >>= 1) s += __shfl_xor_sync(0xffffffffu, s, o);
    if (lane == 0) g_logZ_em[k] = m + logf(s);
}

// ---- D: transition rows, 128-row (16i x 8j) tiles, 512 threads ----
// cp.async double-buffered td_W staging.
// smem bytes: th/Ot 0..133120 | Wt0 133120(36864) | Wt1 169984(36864)
//  (P/Q/TL staging buffers live inside the Wt1 region; dead before chunk1 lands)
//  g 206848(2048) | beta 208896(2048) | tdb 210944(1024) | red 211968(2048)
//  lse 214016(512) -> 214528
#define D_THSTR 520
#define D_OSTR  260
#define D_WSTR  72
#define D_SMEM 214528
__global__ __launch_bounds__(512) void nhmm_kD(
    const float* __restrict__ tlembs, const float* __restrict__ tn_g,
    const float* __restrict__ tn_beta, const float* __restrict__ tdb)
{
    extern __shared__ char sm[];
    __nv_bfloat16* th_s = reinterpret_cast<__nv_bfloat16*>(sm);
    float* Ot           = reinterpret_cast<float*>(sm);           // reuse after mma
    __nv_bfloat16* Wt0  = reinterpret_cast<__nv_bfloat16*>(sm + 133120);
    __nv_bfloat16* Wt1  = reinterpret_cast<__nv_bfloat16*>(sm + 169984);
    __nv_bfloat16* PtB  = reinterpret_cast<__nv_bfloat16*>(sm + 169984);
    __nv_bfloat16* QtB  = reinterpret_cast<__nv_bfloat16*>(sm + 186368);
    __nv_bfloat16* TLiB = reinterpret_cast<__nv_bfloat16*>(sm + 194560);
    __nv_bfloat16* TLjB = reinterpret_cast<__nv_bfloat16*>(sm + 202752);
    float* g_s   = reinterpret_cast<float*>(sm + 206848);
    float* be_s  = reinterpret_cast<float*>(sm + 208896);
    float* tdb_s = reinterpret_cast<float*>(sm + 210944);
    float2* red  = reinterpret_cast<float2*>(sm + 211968);
    float* lse_s = reinterpret_cast<float*>(sm + 214016);

    int ib = blockIdx.x, jb = blockIdx.y;
    int tid = threadIdx.x, warp = tid >> 5, lane = tid & 31;
    int wr = warp >> 1, wc = warp & 1;
    int gid = lane >> 2, tg = lane & 3;

    // stage P (16x512), Q (8x512), TLi (16x256), TLj (8x256) as bf16
    #pragma unroll
    for (int it = 0; it < 2; it++) {
        int e = (tid + it*512) * 8;
        int r = e >> 9, c = e & 511;
        const float4* s4 = reinterpret_cast<const float4*>(&g_P[min(ib*16+r,256)*MDIM + c]);
        *reinterpret_cast<uint4*>(&PtB[r*512 + c]) = f8_to_bf8(s4[0], s4[1]);
    }
    {
        int e = tid * 8;
        int r = e >> 9, c = e & 511;
        const float4* s4 = reinterpret_cast<const float4*>(&g_Q[min(jb*8+r,256)*MDIM + c]);
        *reinterpret_cast<uint4*>(&QtB[r*512 + c]) = f8_to_bf8(s4[0], s4[1]);
    }
    {
        int e = tid * 8;
        int r = e >> 8, c = e & 255;
        const float4* s4 = reinterpret_cast<const float4*>(&tlembs[min(ib*16+r,256)*DIM + c]);
        *reinterpret_cast<uint4*>(&TLiB[r*256 + c]) = f8_to_bf8(s4[0], s4[1]);
    }
    if (tid < 256) {
        int e = tid * 8;
        int r = e >> 8, c = e & 255;
        const float4* s4 = reinterpret_cast<const float4*>(&tlembs[min(jb*8+r,256)*DIM + c]);
        *reinterpret_cast<uint4*>(&TLjB[r*256 + c]) = f8_to_bf8(s4[0], s4[1]);
    }
    g_s[tid] = tn_g[tid];
    be_s[tid] = tn_beta[tid];
    if (tid < KST) tdb_s[tid] = tdb[tid];

    // prefetch td_W chunk0 into Wt0 (doesn't overlap staging buffers)
    {
        #pragma unroll
        for (int u = 0; u < 4; u++) {
            int op = u*512 + tid;          // 0..2047
            int n = op >> 3, seg = (op & 7) * 8;
            cp16(&Wt0[n*D_WSTR + seg], &g_tdw_bf[n*MDIM + 0 + seg]);
        }
        asm volatile("cp.async.commit_group;\n" ::: "memory");
    }
    __syncthreads();

    // th = LN(cat + relu(P[i]+Q[j])) ; warp handles 8 rows, lane owns 16 cols
    for (int q = 0; q < 8; q++) {
        int r = warp*8 + q, ir = r >> 3, jr = r & 7;
        int c0 = lane * 16;
        const uint4* pp = reinterpret_cast<const uint4*>(&PtB[ir*512 + c0]);
        const uint4* qq = reinterpret_cast<const uint4*>(&QtB[jr*512 + c0]);
        const uint4* cc = (c0 < DIM)
            ? reinterpret_cast<const uint4*>(&TLiB[ir*DIM + c0])
            : reinterpret_cast<const uint4*>(&TLjB[jr*DIM + (c0 - DIM)]);
        uint4 pv[2] = {pp[0], pp[1]};
        uint4 qv[2] = {qq[0], qq[1]};
        uint4 cv[2] = {cc[0], cc[1]};
        const unsigned* pw = reinterpret_cast<const unsigned*>(pv);
        const unsigned* qw = reinterpret_cast<const unsigned*>(qv);
        const unsigned* cw = reinterpret_cast<const unsigned*>(cv);
        float vv[16]; float s = 0.f, s2 = 0.f;
        #pragma unroll
        for (int u = 0; u < 8; u++) {
            float2 pf = u2f2(pw[u]), qf = u2f2(qw[u]), cf = u2f2(cw[u]);
            float w0 = cf.x + fmaxf(pf.x + qf.x, 0.f);
            float w1 = cf.y + fmaxf(pf.y + qf.y, 0.f);
            vv[2*u] = w0; vv[2*u+1] = w1;
            s += w0 + w1; s2 += w0*w0 + w1*w1;
        }
        #pragma unroll
        for (int o = 16; o; o >>= 1) {
            s  += __shfl_xor_sync(0xffffffffu, s,  o);
            s2 += __shfl_xor_sync(0xffffffffu, s2, o);
        }
        float mu = s * (1.f/MDIM);
        float rstd = rsqrtf(s2*(1.f/MDIM) - mu*mu + LN_EPS);
        #pragma unroll
        for (int u = 0; u < 2; u++) {
            int cbx = c0 + 8*u;
            const float4* gg = reinterpret_cast<const float4*>(&g_s[cbx]);
            const float4* bb = reinterpret_cast<const float4*>(&be_s[cbx]);
            float4 g0 = gg[0], g1 = gg[1], b0 = bb[0], b1 = bb[1];
            float4 ha, hb;
            ha.x = (vv[8*u  ]-mu)*rstd*g0.x + b0.x;
            ha.y = (vv[8*u+1]-mu)*rstd*g0.y + b0.y;
            ha.z = (vv[8*u+2]-mu)*rstd*g0.z + b0.z;
            ha.w = (vv[8*u+3]-mu)*rstd*g0.w + b0.w;
            hb.x = (vv[8*u+4]-mu)*rstd*g1.x + b1.x;
            hb.y = (vv[8*u+5]-mu)*rstd*g1.y + b1.y;
            hb.z = (vv[8*u+6]-mu)*rstd*g1.z + b1.z;
            hb.w = (vv[8*u+7]-mu)*rstd*g1.w + b1.w;
            *reinterpret_cast<uint4*>(&th_s[r*D_THSTR + cbx]) = f8_to_bf8(ha, hb);
        }
    }
    __syncthreads();   // th visible; P/Q/TL staging region now dead

    // prefetch chunk1 into Wt1 (overwrites dead staging region)
    {
        #pragma unroll
        for (int u = 0; u < 4; u++) {
            int op = u*512 + tid;
            int n = op >> 3, seg = (op & 7) * 8;
            cp16(&Wt1[n*D_WSTR + seg], &g_tdw_bf[n*MDIM + 64 + seg]);
        }
        asm volatile("cp.async.commit_group;\n" ::: "memory");
    }

    unsigned TH_u = smem_u32(th_s);
    unsigned W0_u = smem_u32(Wt0), W1_u = smem_u32(Wt1);
    int a_row = wr*16 + (lane & 15);
    int a_k8  = (lane >> 4) * 8;
    unsigned a_base = TH_u + (unsigned)(a_row*D_THSTR + a_k8)*2u;
    int b_r = lane & 7, b_seg = lane >> 3;
    int b_row0 = ((b_seg >> 1) & 1)*8 + b_r;
    int b_k8 = (b_seg & 1)*8;
    unsigned b_off = (unsigned)(b_row0*D_WSTR + b_k8)*2u;

    float acc[16][4] = {};
    #pragma unroll 1
    for (int c = 0; c < 8; c++) {
        if (c < 7) asm volatile("cp.async.wait_group 1;\n" ::: "memory");
        else       asm volatile("cp.async.wait_group 0;\n" ::: "memory");
        __syncthreads();
        unsigned b_base = ((c & 1) ? W1_u : W0_u) + b_off;
        int kc = c * 64;
        #pragma unroll
        for (int ks = 0; ks < 64; ks += 16) {
            unsigned a0, a1, a2, a3;
            ldsm4(a0, a1, a2, a3, a_base + (unsigned)(kc + ks)*2u);
            #pragma unroll
            for (int e = 0; e < 8; e++) {
                unsigned b0, b1, b2, b3;
                ldsm4(b0, b1, b2, b3,
                      b_base + (unsigned)((wc*128 + e*16)*D_WSTR + ks)*2u);
                mma16816(acc[2*e],   a0, a1, a2, a3, b0, b1);
                mma16816(acc[2*e+1], a0, a1, a2, a3, b2, b3);
            }
        }
        __syncthreads();
        if (c + 2 < 8) {
            __nv_bfloat16* buf = (c & 1) ? Wt1 : Wt0;
            int kc2 = (c + 2) * 64;
            #pragma unroll
            for (int u = 0; u < 4; u++) {
                int op = u*512 + tid;
                int n = op >> 3, seg = (op & 7) * 8;
                cp16(&buf[n*D_WSTR + seg], &g_tdw_bf[n*MDIM + kc2 + seg]);
            }
            asm volatile("cp.async.commit_group;\n" ::: "memory");
        }
    }

    // bias fold + per-row logsumexp
    int rA = wr*16 + gid, rB = rA + 8;
    float m0 = NEGINF, m1 = NEGINF;
    #pragma unroll
    for (int f = 0; f < 16; f++) {
        int n = wc*128 + f*8 + 2*tg;
        acc[f][0] += tdb_s[n]; acc[f][1] += tdb_s[n+1];
        acc[f][2] += tdb_s[n]; acc[f][3] += tdb_s[n+1];
        m0 = fmaxf(m0, fmaxf(acc[f][0], acc[f][1]));
        m1 = fmaxf(m1, fmaxf(acc[f][2], acc[f][3]));
    }
    m0 = fmaxf(m0, __shfl_xor_sync(0xffffffffu, m0, 1));
    m0 = fmaxf(m0, __shfl_xor_sync(0xffffffffu, m0, 2));
    m1 = fmaxf(m1, __shfl_xor_sync(0xffffffffu, m1, 1));
    m1 = fmaxf(m1, __shfl_xor_sync(0xffffffffu, m1, 2));
    float s0 = 0.f, s1 = 0.f;
    #pragma unroll
    for (int f = 0; f < 16; f++) {
        s0 += __expf(acc[f][0]-m0) + __expf(acc[f][1]-m0);
        s1 += __expf(acc[f][2]-m1) + __expf(acc[f][3]-m1);
    }
    s0 += __shfl_xor_sync(0xffffffffu, s0, 1);
    s0 += __shfl_xor_sync(0xffffffffu, s0, 2);
    s1 += __shfl_xor_sync(0xffffffffu, s1, 1);
    s1 += __shfl_xor_sync(0xffffffffu, s1, 2);
    if (tg == 0) { red[rA*2 + wc] = make_float2(m0, s0); red[rB*2 + wc] = make_float2(m1, s1); }
    __syncthreads();
    if (tid < 128) {
        float2 a = red[tid*2], b = red[tid*2+1];
        float M = fmaxf(a.x, b.x);
        lse_s[tid] = M + logf(__expf(a.x-M)*a.y + __expf(b.x-M)*b.y);
    }
    __syncthreads();   // everyone past mma reads -> th_s reusable as Ot

    {
        float lA = lse_s[rA], lB = lse_s[rB];
        #pragma unroll
        for (int f = 0; f < 16; f++) {
            int n = wc*128 + f*8 + 2*tg;
            *reinterpret_cast<float2*>(&Ot[rA*D_OSTR + n]) =
                make_float2(acc[f][0]-lA, acc[f][1]-lA);
            *reinterpret_cast<float2*>(&Ot[rB*D_OSTR + n]) =
                make_float2(acc[f][2]-lB, acc[f][3]-lB);
        }
    }
    __syncthreads();

    {   // coalesced copy Ot -> g_translp
        int row = tid >> 2, kb = (tid & 3) * 64;
        int i = ib*16 + (row >> 3), j = jb*8 + (row & 7);
        if (i < KP1 && j < KP1) {
            const float4* src = reinterpret_cast<const float4*>(&Ot[row*D_OSTR + kb]);
            float4* dst = reinterpret_cast<float4*>(&g_translp[(size_t)(i*KP1 + j)*KST + kb]);
            #pragma unroll
            for (int u = 0; u < 16; u++) dst[u] = src[u];
        }
    }
}

// ---- E: gather + partial reduction ----
__global__ __launch_bounds__(256) void nhmm_kE(
    const int* __restrict__ x, const int* __restrict__ z,
    const float* __restrict__ decW, const float* __restrict__ decb)
{
    __shared__ float part[8];
    int b = blockIdx.x, ty = blockIdx.y;
    int t0 = ty * 64;
    int tid = threadIdx.x, warp = tid >> 5, lane = tid & 31;
    float accw = 0.f;
    for (int q = 0; q < 8; q++) {
        int t = t0 + warp + 8*q;
        int xv = x[t*BBAT + b], zv = z[t*BBAT + b];
        int w0 = (t >= 2) ? z[(t-2)*BBAT + b] : KST;
        int w1 = (t >= 1) ? z[(t-1)*BBAT + b] : KST;
        const float4* ha = reinterpret_cast<const float4*>(&g_h32[zv*DIM]);
        const float4* wa = reinterpret_cast<const float4*>(&decW[(size_t)xv*DIM]);
        float d = 0.f;
        #pragma unroll
        for (int u = 0; u < 2; u++) {
            float4 hv = ha[lane*2+u], wv = wa[lane*2+u];
            d += hv.x*wv.x + hv.y*wv.y + hv.z*wv.z + hv.w*wv.w;
        }
        #pragma unroll
        for (int o = 16; o; o >>= 1) d += __shfl_xor_sync(0xffffffffu, d, o);
        if (lane == 0)
            accw += d + decb[xv] - g_logZ_em[zv]
                  + g_translp[(size_t)(w0*KP1 + w1)*KST + zv];
    }
    if (lane == 0) part[warp] = accw;
    __syncthreads();
    if (tid == 0) {
        float s = 0.f;
        for (int w = 0; w < 8; w++) s += part[w];
        g_epart[b*8 + ty] = s;
    }
}

__global__ __launch_bounds__(BBAT) void nhmm_kEred(float* __restrict__ out)
{
    int b = threadIdx.x;
    float s = 0.f;
    #pragma unroll
    for (int q = 0; q < 8; q++) s += g_epart[b*8 + q];
    out[b] = s;
}

extern "C" void kernel_launch(void* const* d_in, const int* in_sizes, int n_in,
                              void* d_out, int out_size)
{
    const int*   x       = (const int*)d_in[0];
    const int*   z       = (const int*)d_in[1];
    const float* lembs   = (const float*)d_in[2];
    const float* tlembs  = (const float*)d_in[3];
    const float* decW    = (const float*)d_in[4];
    const float* decb    = (const float*)d_in[5];
    const float* emW     = (const float*)d_in[6];
    const float* em_bias = (const float*)d_in[7];
    const float* em_g    = (const float*)d_in[8];
    const float* em_beta = (const float*)d_in[9];
    const float* tdW     = (const float*)d_in[10];
    const float* tdb     = (const float*)d_in[11];
    const float* tmW     = (const float*)d_in[12];
    const float* tm_bias = (const float*)d_in[13];
    const float* tn_g    = (const float*)d_in[14];
    const float* tn_beta = (const float*)d_in[15];
    float* out = (float*)d_out;

    static cudaStream_t s2 = nullptr;
    static cudaEvent_t eFork = nullptr, eJoin = nullptr;
    if (s2 == nullptr) {
        cudaStreamCreateWithFlags(&s2, cudaStreamNonBlocking);
        cudaEventCreateWithFlags(&eFork, cudaEventDisableTiming);
        cudaEventCreateWithFlags(&eJoin, cudaEventDisableTiming);
        cudaFuncSetAttribute(nhmm_kC, cudaFuncAttributeMaxDynamicSharedMemorySize, C_SMEM);
        cudaFuncSetAttribute(nhmm_kD, cudaFuncAttributeMaxDynamicSharedMemorySize, D_SMEM);
    }

    // fork: side chain kA -> kC -> kCred on s2
    cudaEventRecord(eFork, 0);
    cudaStreamWaitEvent(s2, eFork, 0);
    nhmm_kA<<<KST, DIM, 0, s2>>>(lembs, emW, em_bias, em_g, em_beta);
    nhmm_kC<<<NCB, 256, C_SMEM, s2>>>(decW, decb);
    nhmm_kCred<<<KST, 32, 0, s2>>>();

    // main chain: kB -> kConv -> kD on default stream
    nhmm_kB<<<MDIM, 256>>>(tlembs, tmW, tm_bias);
    nhmm_kConv<<<(KST*MDIM + 255)/256, 256>>>(tdW);
    nhmm_kD<<<dim3(17, 33), 512, D_SMEM>>>(tlembs, tn_g, tn_beta, tdb);

    // join, then gather
    cudaEventRecord(eJoin, s2);
    cudaStreamWaitEvent(0, eJoin, 0);
    nhmm_kE<<<dim3(BBAT, 8), 256>>>(x, z, decW, decb);
    nhmm_kEred<<<1, BBAT>>>(out);
}

// round 14
// speedup vs baseline: 2.3049x; 1.1961x over previous
#include <cuda_runtime.h>
#include <cuda_bf16.h>

#define KST   256
#define DIM   256
#define VOC   50000
#define TT    512
#define BBAT  256
#define KP1   257
#define MDIM  512
#define NROWS (KP1*KP1)
#define LN_EPS 1e-5f
#define NEGINF (__int_as_float(0xff800000))
#define NCB   391            // ceil(50000/128)

__device__ __nv_bfloat16 g_h_bf[KST*DIM];
__device__ float g_h32[KST*DIM];
__device__ float g_P[KP1*MDIM];
__device__ float g_Q[KP1*MDIM];
__device__ __nv_bfloat16 g_tdw_bf[KST*MDIM];
__device__ float g_logZ_em[KST];
__device__ float g_em_pmax[KST*NCB];
__device__ float g_em_psum[KST*NCB];
__device__ float g_translp[(size_t)NROWS*KST];
__device__ float g_epart[BBAT*8];

__device__ __forceinline__ void mma16816(float* c,
    unsigned a0, unsigned a1, unsigned a2, unsigned a3, unsigned b0, unsigned b1)
{
    asm volatile(
        "mma.sync.aligned.m16n8k16.row.col.f32.bf16.bf16.f32 "
        "{%0,%1,%2,%3}, {%4,%5,%6,%7}, {%8,%9}, {%0,%1,%2,%3};\n"
        : "+f"(c[0]), "+f"(c[1]), "+f"(c[2]), "+f"(c[3])
        : "r"(a0), "r"(a1), "r"(a2), "r"(a3), "r"(b0), "r"(b1));
}
__device__ __forceinline__ void ldsm4(unsigned& r0, unsigned& r1, unsigned& r2, unsigned& r3,
                                      unsigned addr)
{
    asm volatile("ldmatrix.sync.aligned.m8n8.x4.shared.b16 {%0,%1,%2,%3}, [%4];"
        : "=r"(r0), "=r"(r1), "=r"(r2), "=r"(r3) : "r"(addr));
}
__device__ __forceinline__ unsigned smem_u32(const void* p)
{
    return (unsigned)__cvta_generic_to_shared(p);
}
__device__ __forceinline__ void cp16(void* dst_smem, const void* src)
{
    unsigned d = smem_u32(dst_smem);
    asm volatile("cp.async.cg.shared.global [%0], [%1], 16;\n" :: "r"(d), "l"(src));
}
__device__ __forceinline__ unsigned bf2u(__nv_bfloat162 v)
{
    return *reinterpret_cast<unsigned*>(&v);
}
__device__ __forceinline__ float2 u2f2(unsigned u)
{
    __nv_bfloat162 b = *reinterpret_cast<__nv_bfloat162*>(&u);
    return __bfloat1622float2(b);
}
__device__ __forceinline__ uint4 f8_to_bf8(float4 a, float4 b)
{
    uint4 v;
    v.x = bf2u(__floats2bfloat162_rn(a.x, a.y));
    v.y = bf2u(__floats2bfloat162_rn(a.z, a.w));
    v.z = bf2u(__floats2bfloat162_rn(b.x, b.y));
    v.w = bf2u(__floats2bfloat162_rn(b.z, b.w));
    return v;
}

// ---- A: emission MLP -> h (fp32 + bf16) ; one block per state k ----
__global__ __launch_bounds__(DIM) void nhmm_kA(
    const float* __restrict__ lembs, const float* __restrict__ emW,
    const float* __restrict__ em_bias, const float* __restrict__ em_g,
    const float* __restrict__ em_beta)
{
    __shared__ float le[DIM];
    __shared__ float ws[8], ws2[8];
    int k = blockIdx.x, c = threadIdx.x;
    le[c] = lembs[k*DIM + c];
    __syncthreads();
    const float4* w4 = reinterpret_cast<const float4*>(emW + (size_t)c*DIM);
    float acc = 0.f;
    #pragma unroll 8
    for (int d4 = 0; d4 < DIM/4; d4++) {
        float4 w = w4[d4];
        acc += le[4*d4]*w.x + le[4*d4+1]*w.y + le[4*d4+2]*w.z + le[4*d4+3]*w.w;
    }
    float p = le[c] + fmaxf(acc + em_bias[c], 0.f);
    float s = p, s2 = p*p;
    #pragma unroll
    for (int o = 16; o; o >>= 1) {
        s  += __shfl_xor_sync(0xffffffffu, s,  o);
        s2 += __shfl_xor_sync(0xffffffffu, s2, o);
    }
    if ((c & 31) == 0) { ws[c>>5] = s; ws2[c>>5] = s2; }
    __syncthreads();
    float S = 0.f, S2 = 0.f;
    #pragma unroll
    for (int w = 0; w < 8; w++) { S += ws[w]; S2 += ws2[w]; }
    float mu = S * (1.f/DIM);
    float rstd = rsqrtf(S2*(1.f/DIM) - mu*mu + LN_EPS);
    float h = (p - mu)*rstd*em_g[c] + em_beta[c];
    g_h32[k*DIM + c] = h;
    g_h_bf[k*DIM + c] = __float2bfloat16(h);
}

// ---- B2: P,Q = tlembs @ tm_W halves ; block = 8 i-rows x 256 out cols ----
__global__ __launch_bounds__(256) void nhmm_kB2(
    const float* __restrict__ tlembs, const float* __restrict__ tmW,
    const float* __restrict__ tm_bias)
{
    __shared__ float tl[8][DIM];
    int ib = blockIdx.x;            // 0..32
    int cgrp = blockIdx.y;          // 0..3
    int t = threadIdx.x;
    int i0 = ib*8;
    {   // stage 8 tlembs rows (2048 floats)
        int e = t*8;
        int r = e >> 8, c = e & 255;
        const float4* s4 = reinterpret_cast<const float4*>(&tlembs[min(i0+r,KP1-1)*DIM + c]);
        *reinterpret_cast<float4*>(&tl[r][c])   = s4[0];
        *reinterpret_cast<float4*>(&tl[r][c+4]) = s4[1];
    }
    __syncthreads();
    int cg = cgrp*256 + t;          // 0..1023
    bool isP = cg < MDIM;
    int c = isP ? cg : cg - MDIM;
    const float4* w4 = reinterpret_cast<const float4*>(
        tmW + (size_t)c*MDIM + (isP ? 0 : DIM));
    float acc[8] = {};
    #pragma unroll 8
    for (int d4 = 0; d4 < DIM/4; d4++) {
        float4 w = w4[d4];
        #pragma unroll
        for (int i = 0; i < 8; i++) {
            acc[i] += tl[i][4*d4]*w.x + tl[i][4*d4+1]*w.y
                    + tl[i][4*d4+2]*w.z + tl[i][4*d4+3]*w.w;
        }
    }
    float bias = isP ? tm_bias[c] : 0.f;
    float* dst = isP ? g_P : g_Q;
    #pragma unroll
    for (int i = 0; i < 8; i++)
        if (i0 + i < KP1) dst[(i0+i)*MDIM + c] = acc[i] + bias;
}

// ---- conv: td_W -> bf16 ----
__global__ void nhmm_kConv(const float* __restrict__ tdW)
{
    int idx = blockIdx.x*blockDim.x + threadIdx.x;
    if (idx < KST*MDIM) g_tdw_bf[idx] = __float2bfloat16(tdW[idx]);
}

// ---- C: emission partial logsumexp over V ----
#define C_WSTR 264
#define C_ASTR 264
#define C_SMEM 102912
__global__ __launch_bounds__(256) void nhmm_kC(
    const float* __restrict__ decW, const float* __restrict__ decb)
{
    extern __shared__ char sm[];
    __nv_bfloat16* W_s = reinterpret_cast<__nv_bfloat16*>(sm);
    __nv_bfloat16* A_s = reinterpret_cast<__nv_bfloat16*>(sm + 67584);
    float* decb_s = reinterpret_cast<float*>(sm + 101376);
    float2* red   = reinterpret_cast<float2*>(sm + 101888);

    int cb = blockIdx.x;
    int n0 = cb * 128;
    int tid = threadIdx.x, warp = tid >> 5, lane = tid & 31;
    int wr = warp >> 1, wc = warp & 1;
    int gid = lane >> 2, tg = lane & 3;

    {
        int n = tid >> 1, k0 = (tid & 1) * 128;
        bool valid = (n0 + n) < VOC;
        const float4* src = reinterpret_cast<const float4*>(decW + (size_t)(n0+n)*DIM + k0);
        uint4* dst = reinterpret_cast<uint4*>(&W_s[n*C_WSTR + k0]);
        #pragma unroll
        for (int u = 0; u < 16; u++) {
            float4 a = valid ? src[2*u]   : make_float4(0.f,0.f,0.f,0.f);
            float4 b = valid ? src[2*u+1] : make_float4(0.f,0.f,0.f,0.f);
            dst[u] = f8_to_bf8(a, b);
        }
    }
    if (tid < 128) decb_s[tid] = (n0 + tid < VOC) ? decb[n0 + tid] : 0.f;

    unsigned A_u = smem_u32(A_s), W_u = smem_u32(W_s);
    int a_row = wr*16 + (lane & 15);
    int a_k8  = (lane >> 4) * 8;
    unsigned a_base = A_u + (unsigned)(a_row*C_ASTR + a_k8)*2u;
    int b_r = lane & 7, b_seg = lane >> 3;
    int b_row0 = ((b_seg >> 1) & 1)*8 + b_r;
    int b_k8 = (b_seg & 1)*8;
    unsigned b_base = W_u + (unsigned)(b_row0*C_WSTR + b_k8)*2u;

    for (int rb = 0; rb < 4; rb++) {
        int r0 = rb * 64;
        __syncthreads();
        {
            int row = tid >> 2, kb = (tid & 3) * 64;
            const uint4* src = reinterpret_cast<const uint4*>(&g_h_bf[(r0+row)*DIM + kb]);
            uint4* dst = reinterpret_cast<uint4*>(&A_s[row*C_ASTR + kb]);
            #pragma unroll
            for (int u = 0; u < 8; u++) dst[u] = src[u];
        }
        __syncthreads();

        float acc[8][4] = {};
        #pragma unroll
        for (int k = 0; k < DIM; k += 16) {
            unsigned a0, a1, a2, a3;
            ldsm4(a0, a1, a2, a3, a_base + (unsigned)k*2u);
            #pragma unroll
            for (int e = 0; e < 4; e++) {
                unsigned b0, b1, b2, b3;
                ldsm4(b0, b1, b2, b3,
                      b_base + (unsigned)((wc*64 + e*16)*C_WSTR + k)*2u);
                mma16816(acc[2*e],   a0, a1, a2, a3, b0, b1);
                mma16816(acc[2*e+1], a0, a1, a2, a3, b2, b3);
            }
        }

        int rA = wr*16 + gid, rB = rA + 8;
        float m0 = NEGINF, m1 = NEGINF;
        float v[8][4];
        #pragma unroll
        for (int f = 0; f < 8; f++) {
            int n = wc*64 + f*8 + 2*tg;
            bool ok0 = (n0 + n) < VOC, ok1 = (n0 + n + 1) < VOC;
            v[f][0] = ok0 ? acc[f][0] + decb_s[n]   : NEGINF;
            v[f][1] = ok1 ? acc[f][1] + decb_s[n+1] : NEGINF;
            v[f][2] = ok0 ? acc[f][2] + decb_s[n]   : NEGINF;
            v[f][3] = ok1 ? acc[f][3] + decb_s[n+1] : NEGINF;
            m0 = fmaxf(m0, fmaxf(v[f][0], v[f][1]));
            m1 = fmaxf(m1, fmaxf(v[f][2], v[f][3]));
        }
        m0 = fmaxf(m0, __shfl_xor_sync(0xffffffffu, m0, 1));
        m0 = fmaxf(m0, __shfl_xor_sync(0xffffffffu, m0, 2));
        m1 = fmaxf(m1, __shfl_xor_sync(0xffffffffu, m1, 1));
        m1 = fmaxf(m1, __shfl_xor_sync(0xffffffffu, m1, 2));
        float s0 = 0.f, s1 = 0.f;
        #pragma unroll
        for (int f = 0; f < 8; f++) {
            s0 += __expf(v[f][0]-m0) + __expf(v[f][1]-m0);
            s1 += __expf(v[f][2]-m1) + __expf(v[f][3]-m1);
        }
        s0 += __shfl_xor_sync(0xffffffffu, s0, 1);
        s0 += __shfl_xor_sync(0xffffffffu, s0, 2);
        s1 += __shfl_xor_sync(0xffffffffu, s1, 1);
        s1 += __shfl_xor_sync(0xffffffffu, s1, 2);
        if (tg == 0) {
            red[rA*2 + wc] = make_float2(m0, s0);
            red[rB*2 + wc] = make_float2(m1, s1);
        }
        __syncthreads();
        if (tid < 64) {
            float2 a = red[tid*2], b = red[tid*2+1];
            float M = fmaxf(a.x, b.x);
            g_em_pmax[(r0+tid)*NCB + cb] = M;
            g_em_psum[(r0+tid)*NCB + cb] = __expf(a.x-M)*a.y + __expf(b.x-M)*b.y;
        }
    }
}

// ---- Cred: combine partial lse -> logZ_em ; one warp per state ----
__global__ __launch_bounds__(32) void nhmm_kCred()
{
    int k = blockIdx.x, lane = threadIdx.x;
    float m = NEGINF;
    for (int cb = lane; cb < NCB; cb += 32) m = fmaxf(m, g_em_pmax[k*NCB + cb]);
    #pragma unroll
    for (int o = 16; o; o >>= 1) m = fmaxf(m, __shfl_xor_sync(0xffffffffu, m, o));
    float s = 0.f;
    for (int cb = lane; cb < NCB; cb += 32)
        s += __expf(g_em_pmax[k*NCB + cb] - m) * g_em_psum[k*NCB + cb];
    #pragma unroll
    for (int o = 16; o; o >>= 1) s += __shfl_xor_sync(0xffffffffu, s, o);
    if (lane == 0) g_logZ_em[k] = m + logf(s);
}

// ---- D: transition rows, 64-row (8i x 8j) tiles, 256 threads, 2 CTA/SM ----
// smem: th/Ot 0..66560 | Wt0 66560(20480) | Wt1 87040(20480)
//  staging overlay: PtB 66560(8192) QtB 74752(8192) TLiB 82944(4096) TLjB 87040(4096)
//  g_sb 107520(1024) be_sb 108544(1024) tdb 109568(1024) red 110592(1024)
//  lse 111616(256) -> 111872 (x2 CTA = 223744 <= SM smem)
#define D_THSTR 520
#define D_OSTR  260
#define D_WSTR  40
#define D_SMEM 111872
__global__ __launch_bounds__(256, 2) void nhmm_kD(
    const float* __restrict__ tlembs, const float* __restrict__ tn_g,
    const float* __restrict__ tn_beta, const float* __restrict__ tdb)
{
    extern __shared__ char sm[];
    __nv_bfloat16* th_s = reinterpret_cast<__nv_bfloat16*>(sm);
    float* Ot           = reinterpret_cast<float*>(sm);
    __nv_bfloat16* Wt0  = reinterpret_cast<__nv_bfloat16*>(sm + 66560);
    __nv_bfloat16* Wt1  = reinterpret_cast<__nv_bfloat16*>(sm + 87040);
    __nv_bfloat16* PtB  = reinterpret_cast<__nv_bfloat16*>(sm + 66560);
    __nv_bfloat16* QtB  = reinterpret_cast<__nv_bfloat16*>(sm + 74752);
    __nv_bfloat16* TLiB = reinterpret_cast<__nv_bfloat16*>(sm + 82944);
    __nv_bfloat16* TLjB = reinterpret_cast<__nv_bfloat16*>(sm + 87040);
    __nv_bfloat16* g_sb  = reinterpret_cast<__nv_bfloat16*>(sm + 107520);
    __nv_bfloat16* be_sb = reinterpret_cast<__nv_bfloat16*>(sm + 108544);
    float* tdb_s = reinterpret_cast<float*>(sm + 109568);
    float2* red  = reinterpret_cast<float2*>(sm + 110592);
    float* lse_s = reinterpret_cast<float*>(sm + 111616);

    int ib = blockIdx.x, jb = blockIdx.y;
    int tid = threadIdx.x, warp = tid >> 5, lane = tid & 31;
    int wr = warp >> 1, wc = warp & 1;
    int gid = lane >> 2, tg = lane & 3;

    // stage P (8x512), Q (8x512), TLi (8x256), TLj (8x256) as bf16
    #pragma unroll
    for (int it = 0; it < 2; it++) {
        int e = (tid + it*256) * 8;
        int r = e >> 9, c = e & 511;
        const float4* s4 = reinterpret_cast<const float4*>(&g_P[min(ib*8+r,256)*MDIM + c]);
        *reinterpret_cast<uint4*>(&PtB[r*512 + c]) = f8_to_bf8(s4[0], s4[1]);
    }
    #pragma unroll
    for (int it = 0; it < 2; it++) {
        int e = (tid + it*256) * 8;
        int r = e >> 9, c = e & 511;
        const float4* s4 = reinterpret_cast<const float4*>(&g_Q[min(jb*8+r,256)*MDIM + c]);
        *reinterpret_cast<uint4*>(&QtB[r*512 + c]) = f8_to_bf8(s4[0], s4[1]);
    }
    {
        int e = tid * 8;
        int r = e >> 8, c = e & 255;
        const float4* s4 = reinterpret_cast<const float4*>(&tlembs[min(ib*8+r,256)*DIM + c]);
        *reinterpret_cast<uint4*>(&TLiB[r*256 + c]) = f8_to_bf8(s4[0], s4[1]);
        const float4* t4 = reinterpret_cast<const float4*>(&tlembs[min(jb*8+r,256)*DIM + c]);
        *reinterpret_cast<uint4*>(&TLjB[r*256 + c]) = f8_to_bf8(t4[0], t4[1]);
    }
    {
        float2 gv = *reinterpret_cast<const float2*>(&tn_g[2*tid]);
        reinterpret_cast<__nv_bfloat162*>(g_sb)[tid] = __floats2bfloat162_rn(gv.x, gv.y);
        float2 bv = *reinterpret_cast<const float2*>(&tn_beta[2*tid]);
        reinterpret_cast<__nv_bfloat162*>(be_sb)[tid] = __floats2bfloat162_rn(bv.x, bv.y);
    }
    if (tid < KST) tdb_s[tid] = tdb[tid];
    __syncthreads();

    // th = LN(cat + relu(P[i]+Q[j])) ; warp handles 8 rows, lane owns 16 cols
    for (int q = 0; q < 8; q++) {
        int r = warp*8 + q, ir = r >> 3, jr = r & 7;
        int c0 = lane * 16;
        const uint4* pp = reinterpret_cast<const uint4*>(&PtB[ir*512 + c0]);
        const uint4* qq = reinterpret_cast<const uint4*>(&QtB[jr*512 + c0]);
        const uint4* cc = (c0 < DIM)
            ? reinterpret_cast<const uint4*>(&TLiB[ir*DIM + c0])
            : reinterpret_cast<const uint4*>(&TLjB[jr*DIM + (c0 - DIM)]);
        uint4 pv[2] = {pp[0], pp[1]};
        uint4 qv[2] = {qq[0], qq[1]};
        uint4 cv[2] = {cc[0], cc[1]};
        const unsigned* pw = reinterpret_cast<const unsigned*>(pv);
        const unsigned* qw = reinterpret_cast<const unsigned*>(qv);
        const unsigned* cw = reinterpret_cast<const unsigned*>(cv);
        float vv[16]; float s = 0.f, s2 = 0.f;
        #pragma unroll
        for (int u = 0; u < 8; u++) {
            float2 pf = u2f2(pw[u]), qf = u2f2(qw[u]), cf = u2f2(cw[u]);
            float w0 = cf.x + fmaxf(pf.x + qf.x, 0.f);
            float w1 = cf.y + fmaxf(pf.y + qf.y, 0.f);
            vv[2*u] = w0; vv[2*u+1] = w1;
            s += w0 + w1; s2 += w0*w0 + w1*w1;
        }
        #pragma unroll
        for (int o = 16; o; o >>= 1) {
            s  += __shfl_xor_sync(0xffffffffu, s,  o);
            s2 += __shfl_xor_sync(0xffffffffu, s2, o);
        }
        float mu = s * (1.f/MDIM);
        float rstd = rsqrtf(s2*(1.f/MDIM) - mu*mu + LN_EPS);
        #pragma unroll
        for (int u = 0; u < 2; u++) {
            int cbx = c0 + 8*u;
            uint4 gg = *reinterpret_cast<const uint4*>(&g_sb[cbx]);
            uint4 bb = *reinterpret_cast<const uint4*>(&be_sb[cbx]);
            const unsigned* gw = reinterpret_cast<const unsigned*>(&gg);
            const unsigned* bw = reinterpret_cast<const unsigned*>(&bb);
            float2 g0 = u2f2(gw[0]), g1 = u2f2(gw[1]), g2 = u2f2(gw[2]), g3 = u2f2(gw[3]);
            float2 b0 = u2f2(bw[0]), b1 = u2f2(bw[1]), b2 = u2f2(bw[2]), b3 = u2f2(bw[3]);
            float4 ha, hb;
            ha.x = (vv[8*u  ]-mu)*rstd*g0.x + b0.x;
            ha.y = (vv[8*u+1]-mu)*rstd*g0.y + b0.y;
            ha.z = (vv[8*u+2]-mu)*rstd*g1.x + b1.x;
            ha.w = (vv[8*u+3]-mu)*rstd*g1.y + b1.y;
            hb.x = (vv[8*u+4]-mu)*rstd*g2.x + b2.x;
            hb.y = (vv[8*u+5]-mu)*rstd*g2.y + b2.y;
            hb.z = (vv[8*u+6]-mu)*rstd*g3.x + b3.x;
            hb.w = (vv[8*u+7]-mu)*rstd*g3.y + b3.y;
            *reinterpret_cast<uint4*>(&th_s[r*D_THSTR + cbx]) = f8_to_bf8(ha, hb);
        }
    }
    __syncthreads();   // th visible; staging region (inside Wt0/Wt1) now dead

    // prefetch chunks 0 and 1
    #pragma unroll
    for (int u = 0; u < 4; u++) {
        int op = u*256 + tid;            // 0..1023
        int n = op >> 2, seg = (op & 3) * 8;
        cp16(&Wt0[n*D_WSTR + seg], &g_tdw_bf[n*MDIM + 0 + seg]);
    }
    asm volatile("cp.async.commit_group;\n" ::: "memory");
    #pragma unroll
    for (int u = 0; u < 4; u++) {
        int op = u*256 + tid;
        int n = op >> 2, seg = (op & 3) * 8;
        cp16(&Wt1[n*D_WSTR + seg], &g_tdw_bf[n*MDIM + 32 + seg]);
    }
    asm volatile("cp.async.commit_group;\n" ::: "memory");

    unsigned TH_u = smem_u32(th_s);
    unsigned W0_u = smem_u32(Wt0), W1_u = smem_u32(Wt1);
    int a_row = wr*16 + (lane & 15);
    int a_k8  = (lane >> 4) * 8;
    unsigned a_base = TH_u + (unsigned)(a_row*D_THSTR + a_k8)*2u;
    int b_r = lane & 7, b_seg = lane >> 3;
    int b_row0 = ((b_seg >> 1) & 1)*8 + b_r;
    int b_k8 = (b_seg & 1)*8;
    unsigned b_off = (unsigned)(b_row0*D_WSTR + b_k8)*2u;

    float acc[16][4] = {};
    #pragma unroll 1
    for (int c = 0; c < 16; c++) {
        if (c < 15) asm volatile("cp.async.wait_group 1;\n" ::: "memory");
        else        asm volatile("cp.async.wait_group 0;\n" ::: "memory");
        __syncthreads();
        unsigned b_base = ((c & 1) ? W1_u : W0_u) + b_off;
        int kc = c * 32;
        #pragma unroll
        for (int ks = 0; ks < 32; ks += 16) {
            unsigned a0, a1, a2, a3;
            ldsm4(a0, a1, a2, a3, a_base + (unsigned)(kc + ks)*2u);
            #pragma unroll
            for (int e = 0; e < 8; e++) {
                unsigned b0, b1, b2, b3;
                ldsm4(b0, b1, b2, b3,
                      b_base + (unsigned)((wc*128 + e*16)*D_WSTR + ks)*2u);
                mma16816(acc[2*e],   a0, a1, a2, a3, b0, b1);
                mma16816(acc[2*e+1], a0, a1, a2, a3, b2, b3);
            }
        }
        __syncthreads();
        if (c + 2 < 16) {
            __nv_bfloat16* buf = (c & 1) ? Wt1 : Wt0;
            int kc2 = (c + 2) * 32;
            #pragma unroll
            for (int u = 0; u < 4; u++) {
                int op = u*256 + tid;
                int n = op >> 2, seg = (op & 3) * 8;
                cp16(&buf[n*D_WSTR + seg], &g_tdw_bf[n*MDIM + kc2 + seg]);
            }
            asm volatile("cp.async.commit_group;\n" ::: "memory");
        }
    }

    // bias fold + per-row logsumexp
    int rA = wr*16 + gid, rB = rA + 8;
    float m0 = NEGINF, m1 = NEGINF;
    #pragma unroll
    for (int f = 0; f < 16; f++) {
        int n = wc*128 + f*8 + 2*tg;
        acc[f][0] += tdb_s[n]; acc[f][1] += tdb_s[n+1];
        acc[f][2] += tdb_s[n]; acc[f][3] += tdb_s[n+1];
        m0 = fmaxf(m0, fmaxf(acc[f][0], acc[f][1]));
        m1 = fmaxf(m1, fmaxf(acc[f][2], acc[f][3]));
    }
    m0 = fmaxf(m0, __shfl_xor_sync(0xffffffffu, m0, 1));
    m0 = fmaxf(m0, __shfl_xor_sync(0xffffffffu, m0, 2));
    m1 = fmaxf(m1, __shfl_xor_sync(0xffffffffu, m1, 1));
    m1 = fmaxf(m1, __shfl_xor_sync(0xffffffffu, m1, 2));
    float s0 = 0.f, s1 = 0.f;
    #pragma unroll
    for (int f = 0; f < 16; f++) {
        s0 += __expf(acc[f][0]-m0) + __expf(acc[f][1]-m0);
        s1 += __expf(acc[f][2]-m1) + __expf(acc[f][3]-m1);
    }
    s0 += __shfl_xor_sync(0xffffffffu, s0, 1);
    s0 += __shfl_xor_sync(0xffffffffu, s0, 2);
    s1 += __shfl_xor_sync(0xffffffffu, s1, 1);
    s1 += __shfl_xor_sync(0xffffffffu, s1, 2);
    if (tg == 0) { red[rA*2 + wc] = make_float2(m0, s0); red[rB*2 + wc] = make_float2(m1, s1); }
    __syncthreads();
    if (tid < 64) {
        float2 a = red[tid*2], b = red[tid*2+1];
        float M = fmaxf(a.x, b.x);
        lse_s[tid] = M + logf(__expf(a.x-M)*a.y + __expf(b.x-M)*b.y);
    }
    __syncthreads();   // everyone past mma reads -> th_s reusable as Ot

    {
        float lA = lse_s[rA], lB = lse_s[rB];
        #pragma unroll
        for (int f = 0; f < 16; f++) {
            int n = wc*128 + f*8 + 2*tg;
            *reinterpret_cast<float2*>(&Ot[rA*D_OSTR + n]) =
                make_float2(acc[f][0]-lA, acc[f][1]-lA);
            *reinterpret_cast<float2*>(&Ot[rB*D_OSTR + n]) =
                make_float2(acc[f][2]-lB, acc[f][3]-lB);
        }
    }
    __syncthreads();

    {   // coalesced copy Ot -> g_translp (64 rows x 256 f32)
        int row = tid >> 2, kb = (tid & 3) * 64;
        int i = ib*8 + (row >> 3), j = jb*8 + (row & 7);
        if (i < KP1 && j < KP1) {
            const float4* src = reinterpret_cast<const float4*>(&Ot[row*D_OSTR + kb]);
            float4* dst = reinterpret_cast<float4*>(&g_translp[(size_t)(i*KP1 + j)*KST + kb]);
            #pragma unroll
            for (int u = 0; u < 16; u++) dst[u] = src[u];
        }
    }
}

// ---- E: gather + partial reduction ----
__global__ __launch_bounds__(256) void nhmm_kE(
    const int* __restrict__ x, const int* __restrict__ z,
    const float* __restrict__ decW, const float* __restrict__ decb)
{
    __shared__ float part[8];
    int b = blockIdx.x, ty = blockIdx.y;
    int t0 = ty * 64;
    int tid = threadIdx.x, warp = tid >> 5, lane = tid & 31;
    float accw = 0.f;
    for (int q = 0; q < 8; q++) {
        int t = t0 + warp + 8*q;
        int xv = x[t*BBAT + b], zv = z[t*BBAT + b];
        int w0 = (t >= 2) ? z[(t-2)*BBAT + b] : KST;
        int w1 = (t >= 1) ? z[(t-1)*BBAT + b] : KST;
        const float4* ha = reinterpret_cast<const float4*>(&g_h32[zv*DIM]);
        const float4* wa = reinterpret_cast<const float4*>(&decW[(size_t)xv*DIM]);
        float d = 0.f;
        #pragma unroll
        for (int u = 0; u < 2; u++) {
            float4 hv = ha[lane*2+u], wv = wa[lane*2+u];
            d += hv.x*wv.x + hv.y*wv.y + hv.z*wv.z + hv.w*wv.w;
        }
        #pragma unroll
        for (int o = 16; o; o >>= 1) d += __shfl_xor_sync(0xffffffffu, d, o);
        if (lane == 0)
            accw += d + decb[xv] - g_logZ_em[zv]
                  + g_translp[(size_t)(w0*KP1 + w1)*KST + zv];
    }
    if (lane == 0) part[warp] = accw;
    __syncthreads();
    if (tid == 0) {
        float s = 0.f;
        for (int w = 0; w < 8; w++) s += part[w];
        g_epart[b*8 + ty] = s;
    }
}

__global__ __launch_bounds__(BBAT) void nhmm_kEred(float* __restrict__ out)
{
    int b = threadIdx.x;
    float s = 0.f;
    #pragma unroll
    for (int q = 0; q < 8; q++) s += g_epart[b*8 + q];
    out[b] = s;
}

extern "C" void kernel_launch(void* const* d_in, const int* in_sizes, int n_in,
                              void* d_out, int out_size)
{
    const int*   x       = (const int*)d_in[0];
    const int*   z       = (const int*)d_in[1];
    const float* lembs   = (const float*)d_in[2];
    const float* tlembs  = (const float*)d_in[3];
    const float* decW    = (const float*)d_in[4];
    const float* decb    = (const float*)d_in[5];
    const float* emW     = (const float*)d_in[6];
    const float* em_bias = (const float*)d_in[7];
    const float* em_g    = (const float*)d_in[8];
    const float* em_beta = (const float*)d_in[9];
    const float* tdW     = (const float*)d_in[10];
    const float* tdb     = (const float*)d_in[11];
    const float* tmW     = (const float*)d_in[12];
    const float* tm_bias = (const float*)d_in[13];
    const float* tn_g    = (const float*)d_in[14];
    const float* tn_beta = (const float*)d_in[15];
    float* out = (float*)d_out;

    static cudaStream_t s2 = nullptr;
    static cudaEvent_t eFork = nullptr, eJoin = nullptr;
    if (s2 == nullptr) {
        cudaStreamCreateWithFlags(&s2, cudaStreamNonBlocking);
        cudaEventCreateWithFlags(&eFork, cudaEventDisableTiming);
        cudaEventCreateWithFlags(&eJoin, cudaEventDisableTiming);
        cudaFuncSetAttribute(nhmm_kC, cudaFuncAttributeMaxDynamicSharedMemorySize, C_SMEM);
        cudaFuncSetAttribute(nhmm_kD, cudaFuncAttributeMaxDynamicSharedMemorySize, D_SMEM);
    }

    // fork: side chain kA -> kC -> kCred on s2
    cudaEventRecord(eFork, 0);
    cudaStreamWaitEvent(s2, eFork, 0);
    nhmm_kA<<<KST, DIM, 0, s2>>>(lembs, emW, em_bias, em_g, em_beta);
    nhmm_kC<<<NCB, 256, C_SMEM, s2>>>(decW, decb);
    nhmm_kCred<<<KST, 32, 0, s2>>>();

    // main chain: kB2 -> kConv -> kD on default stream
    nhmm_kB2<<<dim3(33, 4), 256>>>(tlembs, tmW, tm_bias);
    nhmm_kConv<<<(KST*MDIM + 255)/256, 256>>>(tdW);
    nhmm_kD<<<dim3(33, 33), 256, D_SMEM>>>(tlembs, tn_g, tn_beta, tdb);

    // join, then gather
    cudaEventRecord(eJoin, s2);
    cudaStreamWaitEvent(0, eJoin, 0);
    nhmm_kE<<<dim3(BBAT, 8), 256>>>(x, z, decW, decb);
    nhmm_kEred<<<1, BBAT>>>(out);
}